// round 7
// baseline (speedup 1.0000x reference)
#include <cuda_runtime.h>
#include <math.h>

// ---------------- scratch (static __device__, allocation-free) ----------------
__device__ float g_sg [256 * 10000];        // savgol output
__device__ float g_y0 [256 * 64 * 624];     // conv block 0 out (b,c,p); reused as layer1 hs
__device__ float g_seq[77 * 256 * 128];     // conv block 1 out, (t,b,c)
__device__ float g_xp [77 * 256 * 1024];    // lstm input projection (t,b,4H), reused per layer
__device__ float g_hs0[77 * 256 * 256];     // layer0 hidden sequence (t,b,H)
__device__ float g_f1 [256 * 512];
__device__ float g_f2 [256 * 512];

// SG(11,3) interior smoothing taps (symmetric): [-36,9,44,69,84,89,84,69,44,9,-36]/429
__constant__ float c_sg[11] = {
    -36.f/429.f, 9.f/429.f, 44.f/429.f, 69.f/429.f, 84.f/429.f, 89.f/429.f,
    84.f/429.f, 69.f/429.f, 44.f/429.f, 9.f/429.f, -36.f/429.f };

// ---------------- savgol ----------------
__device__ __forceinline__ void sg_fit(const float* __restrict__ xw, double a[4]) {
    double m0 = 0, m1 = 0, m2 = 0, m3 = 0;
    #pragma unroll
    for (int w = 0; w < 11; w++) {
        double y = (double)xw[w]; double t = (double)w;
        m0 += y; m1 += y * t; m2 += y * t * t; m3 += y * t * t * t;
    }
    double M[4][5] = {
        {11.0,    55.0,     385.0,     3025.0,    m0},
        {55.0,    385.0,    3025.0,    25333.0,   m1},
        {385.0,   3025.0,   25333.0,   220825.0,  m2},
        {3025.0,  25333.0,  220825.0,  1978405.0, m3}};
    #pragma unroll
    for (int i = 0; i < 4; i++) {
        double p = M[i][i];
        #pragma unroll
        for (int j = i; j < 5; j++) M[i][j] /= p;
        #pragma unroll
        for (int r = 0; r < 4; r++) {
            if (r != i) {
                double f = M[r][i];
                #pragma unroll
                for (int j = i; j < 5; j++) M[r][j] -= f * M[i][j];
            }
        }
    }
    a[0] = M[0][4]; a[1] = M[1][4]; a[2] = M[2][4]; a[3] = M[3][4];
}

__global__ __launch_bounds__(256) void savgol_kernel(const float* __restrict__ x) {
    int b = blockIdx.y;
    int i = blockIdx.x * 256 + threadIdx.x;
    if (i >= 10000) return;
    const float* xr = x + (size_t)b * 10000;
    float* o = g_sg + (size_t)b * 10000;
    if (i >= 5 && i < 9995) {
        float acc = 0.f;
        #pragma unroll
        for (int j = 0; j < 11; j++) acc = fmaf(xr[i - 5 + j], c_sg[j], acc);
        o[i] = acc;
    } else if (i < 5) {
        double a[4]; sg_fit(xr, a);
        double t = (double)i;
        o[i] = (float)(a[0] + t * (a[1] + t * (a[2] + t * a[3])));
    } else {
        double a[4]; sg_fit(xr + 9989, a);
        double t = (double)(i - 9989);
        o[i] = (float)(a[0] + t * (a[1] + t * (a[2] + t * a[3])));
    }
}

// ---------------- conv block 0 ----------------
__global__ __launch_bounds__(256) void conv0_kernel(
    const float* __restrict__ w, const float* __restrict__ bias,
    const float* __restrict__ bg, const float* __restrict__ bb,
    const float* __restrict__ bm, const float* __restrict__ bv) {
    __shared__ float in_s[2064];
    __shared__ float ws[64][17];
    __shared__ float scs[64], shs[64], bss[64];
    int b = blockIdx.y;
    int p0 = blockIdx.x * 128;
    int tid = threadIdx.x;
    int base = 16 * p0;
    for (int i = tid; i < 2064; i += 256) {
        int col = base + i;
        in_s[i] = (col < 10000) ? g_sg[(size_t)b * 10000 + col] : 0.f;
    }
    for (int i = tid; i < 1024; i += 256) ws[i >> 4][i & 15] = w[i];
    if (tid < 64) {
        float sc = bg[tid] * rsqrtf(bv[tid] + 1e-5f);
        scs[tid] = sc;
        shs[tid] = bb[tid] - bm[tid] * sc;
        bss[tid] = bias[tid];
    }
    __syncthreads();
    int p = p0 + (tid & 127);
    int cb = (tid >> 7) * 32;
    if (p >= 624) return;
    float xr[24];
    int lb = 16 * (tid & 127);
    #pragma unroll
    for (int k = 0; k < 24; k++) xr[k] = in_s[lb + k];
    #pragma unroll 4
    for (int c = cb; c < cb + 32; c++) {
        float s1 = 0.f, s2 = 0.f;
        #pragma unroll
        for (int k = 0; k < 16; k++) {
            float wv = ws[c][k];
            s1 = fmaf(wv, xr[k], s1);
            s2 = fmaf(wv, xr[k + 8], s2);
        }
        float m = fmaxf(fmaxf(s1, s2) + bss[c], 0.f);
        g_y0[((size_t)b * 64 + c) * 624 + p] = scs[c] * m + shs[c];
    }
}

// ---------------- conv block 1 (v3: 8oc x 4pos microtile, 32 pooled/CTA) ----------------
#define C1_IN   (64 * 260)
#define C1_WS   (4 * 8 * 128)
#define C1_SMEM ((C1_IN + C1_WS + 3 * 128) * 4)

__global__ __launch_bounds__(256) void conv1_kernel(
    const float* __restrict__ w, const float* __restrict__ bias,
    const float* __restrict__ bg, const float* __restrict__ bb,
    const float* __restrict__ bm, const float* __restrict__ bv) {
    extern __shared__ float c1s[];
    float* in_s = c1s;                       // [64][260]
    float* ws   = c1s + C1_IN;               // [4][8][128]
    float* scs  = ws + C1_WS;
    float* shs  = scs + 128;
    float* bss  = shs + 128;

    int b = blockIdx.y;
    int p0 = blockIdx.x * 32;
    int tid = threadIdx.x;
    int cg = tid & 15, pg = tid >> 4;        // 8 oc per cg, 2 pooled (4 conv pos) per pg

    for (int i = tid; i < C1_IN; i += 256) {
        int ic = i / 260, cc = i % 260;
        int col = 8 * p0 + cc;
        in_s[i] = (col < 624) ? g_y0[((size_t)b * 64 + ic) * 624 + col] : 0.f;
    }
    if (tid < 128) {
        float sc = bg[tid] * rsqrtf(bv[tid] + 1e-5f);
        scs[tid] = sc;
        shs[tid] = bb[tid] - bm[tid] * sc;
        bss[tid] = bias[tid];
    }
    float acc[8][4];
    #pragma unroll
    for (int i = 0; i < 8; i++)
        #pragma unroll
        for (int j = 0; j < 4; j++) acc[i][j] = 0.f;

    int ocl = tid & 127, half = tid >> 7;
    for (int ic0 = 0; ic0 < 64; ic0 += 4) {
        __syncthreads();
        #pragma unroll
        for (int il = 0; il < 2; il++) {
            int icl = half * 2 + il;
            const float4* src = (const float4*)(w + ((size_t)ocl * 64 + ic0 + icl) * 8);
            float4 v0 = src[0], v1 = src[1];
            float* wd = ws + icl * 1024 + ocl;
            wd[0 * 128] = v0.x; wd[1 * 128] = v0.y; wd[2 * 128] = v0.z; wd[3 * 128] = v0.w;
            wd[4 * 128] = v1.x; wd[5 * 128] = v1.y; wd[6 * 128] = v1.z; wd[7 * 128] = v1.w;
        }
        __syncthreads();
        #pragma unroll
        for (int icl = 0; icl < 4; icl++) {
            #pragma unroll
            for (int t = 0; t < 8; t++) {
                float4 wa = *(const float4*)&ws[icl * 1024 + t * 128 + cg * 8];
                float4 wb = *(const float4*)&ws[icl * 1024 + t * 128 + cg * 8 + 4];
                const float* ir = in_s + (ic0 + icl) * 260 + 16 * pg + t;
                #pragma unroll
                for (int qc = 0; qc < 4; qc++) {
                    float iv = ir[4 * qc];
                    acc[0][qc] = fmaf(wa.x, iv, acc[0][qc]);
                    acc[1][qc] = fmaf(wa.y, iv, acc[1][qc]);
                    acc[2][qc] = fmaf(wa.z, iv, acc[2][qc]);
                    acc[3][qc] = fmaf(wa.w, iv, acc[3][qc]);
                    acc[4][qc] = fmaf(wb.x, iv, acc[4][qc]);
                    acc[5][qc] = fmaf(wb.y, iv, acc[5][qc]);
                    acc[6][qc] = fmaf(wb.z, iv, acc[6][qc]);
                    acc[7][qc] = fmaf(wb.w, iv, acc[7][qc]);
                }
            }
        }
    }
    #pragma unroll
    for (int pp = 0; pp < 2; pp++) {
        int p = p0 + 2 * pg + pp;
        if (p >= 77) continue;
        float ov[8];
        #pragma unroll
        for (int i = 0; i < 8; i++) {
            int oc = 8 * cg + i;
            float m = fmaxf(acc[i][2 * pp], acc[i][2 * pp + 1]);
            float v = fmaxf(m + bss[oc], 0.f);
            ov[i] = scs[oc] * v + shs[oc];
        }
        float* dst = &g_seq[((size_t)p * 256 + b) * 128 + 8 * cg];
        *(float4*)dst = make_float4(ov[0], ov[1], ov[2], ov[3]);
        *(float4*)(dst + 4) = make_float4(ov[4], ov[5], ov[6], ov[7]);
    }
}

// ---------------- input-projection GEMM: g_xp = A @ Wih^T + (bih + bhh) ----------------
__global__ __launch_bounds__(256) void gemm_xproj_kernel(
    int src, const float* __restrict__ Wih,
    const float* __restrict__ b1, const float* __restrict__ b2) {
    __shared__ float As[16][132];
    __shared__ float Ws[16][132];
    const int K = src ? 256 : 128;
    const float* A = src ? g_hs0 : g_seq;
    int n0 = blockIdx.x * 128, m0 = blockIdx.y * 128;
    int tid = threadIdx.x;
    int lr = tid >> 2, lq = tid & 3;
    int tx = tid & 15, ty = tid >> 4;
    float acc[8][8];
    #pragma unroll
    for (int i = 0; i < 8; i++)
        #pragma unroll
        for (int j = 0; j < 8; j++) acc[i][j] = 0.f;

    const float* a0p = A + (size_t)(m0 + lr) * K + 4 * lq;
    const float* a1p = A + (size_t)(m0 + lr + 64) * K + 4 * lq;
    const float* w0p = Wih + (size_t)(n0 + lr) * K + 4 * lq;
    const float* w1p = Wih + (size_t)(n0 + lr + 64) * K + 4 * lq;

    float4 pa0 = *(const float4*)a0p;
    float4 pa1 = *(const float4*)a1p;
    float4 pw0 = *(const float4*)w0p;
    float4 pw1 = *(const float4*)w1p;

    int nch = K >> 4;
    for (int c = 0; c < nch; c++) {
        As[4*lq+0][lr] = pa0.x; As[4*lq+1][lr] = pa0.y; As[4*lq+2][lr] = pa0.z; As[4*lq+3][lr] = pa0.w;
        As[4*lq+0][lr+64] = pa1.x; As[4*lq+1][lr+64] = pa1.y; As[4*lq+2][lr+64] = pa1.z; As[4*lq+3][lr+64] = pa1.w;
        Ws[4*lq+0][lr] = pw0.x; Ws[4*lq+1][lr] = pw0.y; Ws[4*lq+2][lr] = pw0.z; Ws[4*lq+3][lr] = pw0.w;
        Ws[4*lq+0][lr+64] = pw1.x; Ws[4*lq+1][lr+64] = pw1.y; Ws[4*lq+2][lr+64] = pw1.z; Ws[4*lq+3][lr+64] = pw1.w;
        __syncthreads();
        if (c + 1 < nch) {
            int k0 = (c + 1) * 16;
            pa0 = *(const float4*)(a0p + k0);
            pa1 = *(const float4*)(a1p + k0);
            pw0 = *(const float4*)(w0p + k0);
            pw1 = *(const float4*)(w1p + k0);
        }
        #pragma unroll
        for (int kk = 0; kk < 16; kk++) {
            float a[8], bb[8];
            *(float4*)&a[0]  = *(const float4*)&As[kk][8 * ty];
            *(float4*)&a[4]  = *(const float4*)&As[kk][8 * ty + 4];
            *(float4*)&bb[0] = *(const float4*)&Ws[kk][8 * tx];
            *(float4*)&bb[4] = *(const float4*)&Ws[kk][8 * tx + 4];
            #pragma unroll
            for (int i = 0; i < 8; i++)
                #pragma unroll
                for (int j = 0; j < 8; j++)
                    acc[i][j] = fmaf(a[i], bb[j], acc[i][j]);
        }
        __syncthreads();
    }
    float bv[8];
    #pragma unroll
    for (int j = 0; j < 8; j++) {
        int n = n0 + 8 * tx + j;
        bv[j] = b1[n] + b2[n];
    }
    #pragma unroll
    for (int i = 0; i < 8; i++) {
        size_t row = (size_t)(m0 + 8 * ty + i) * 1024 + n0 + 8 * tx;
        float4 o0 = make_float4(acc[i][0]+bv[0], acc[i][1]+bv[1], acc[i][2]+bv[2], acc[i][3]+bv[3]);
        float4 o1 = make_float4(acc[i][4]+bv[4], acc[i][5]+bv[5], acc[i][6]+bv[6], acc[i][7]+bv[7]);
        *(float4*)&g_xp[row]     = o0;
        *(float4*)&g_xp[row + 4] = o1;
    }
}

// ---------------- persistent LSTM layer (v5: 8-CTA clusters, cluster barrier) ----------------
// Grid 128 = 16 clusters x 8 CTAs. Cluster = 16-batch tile; CTA rank owns
// 32 hidden x 4 gates (128 gatecols). Whh slice in 128 regs/thread:
// warp q = k-slice [32q,32q+32), lane owns gatecols 4*lane..4*lane+3.
// Partials ps[8][16][128]; h exchanged via global + barrier.cluster.
#define HSP 260
#define PS_OFF (16 * HSP)
#define CS_OFF (PS_OFF + 8 * 16 * 128)
#define LSTM_SMEM ((16 * HSP + 8 * 16 * 128 + 512) * 4)

__device__ __forceinline__ float sigf(float x) {
    return __fdividef(1.f, 1.f + __expf(-x));
}
__device__ __forceinline__ float tanhfast(float x) {
    return 2.f * sigf(2.f * x) - 1.f;
}

__global__ __launch_bounds__(256) __cluster_dims__(8, 1, 1)
void lstm_persist_kernel(int layer, const float* __restrict__ Whh) {
    extern __shared__ float sm[];
    float* hs_s = sm;                 // [16][HSP] h_prev tile, b-major
    float* ps   = sm + PS_OFF;        // [8][16][128] split-K partials
    float* c_s  = sm + CS_OFF;        // [512] cell state (16 b x 32 h)

    int tid = threadIdx.x;
    int q = tid >> 5;                 // warp = k-slice
    int lane = tid & 31;
    int rank = blockIdx.x & 7;        // gatecol tile
    int bt = blockIdx.x >> 3;         // batch tile
    int b0 = bt * 16;
    int h0 = rank * 32;
    float* hs = layer ? g_y0 : g_hs0;

    // ---- Whh slice into registers (once per launch): wreg[i][k] ----
    float wreg[4][32];
    #pragma unroll
    for (int i = 0; i < 4; i++) {
        int gc = 4 * lane + i;
        int row = (gc >> 5) * 256 + h0 + (gc & 31);
        const float* wp = Whh + (size_t)row * 256 + q * 32;
        #pragma unroll
        for (int k = 0; k < 32; k += 4) {
            float4 v = *(const float4*)(wp + k);
            wreg[i][k + 0] = v.x; wreg[i][k + 1] = v.y;
            wreg[i][k + 2] = v.z; wreg[i][k + 3] = v.w;
        }
    }
    c_s[2 * tid] = 0.f;
    c_s[2 * tid + 1] = 0.f;

    for (int t = 0; t < 77; t++) {
        if (t > 0)
            asm volatile("barrier.cluster.wait.aligned;" ::: "memory");

        // ---- stage h_prev tile ----
        {
            int r = tid >> 4, seg = tid & 15;
            float* dst = hs_s + r * HSP + seg * 16;
            if (t == 0) {
                #pragma unroll
                for (int i = 0; i < 16; i += 4)
                    *(float4*)&dst[i] = make_float4(0.f, 0.f, 0.f, 0.f);
            } else {
                const float* src = hs + (size_t)(t - 1) * 65536 + (size_t)(b0 + r) * 256 + seg * 16;
                #pragma unroll
                for (int i = 0; i < 16; i += 4)
                    *(float4*)&dst[i] = *(const float4*)&src[i];
            }
        }
        __syncthreads();

        // ---- split-K GEMM: 16 batches x 4 gatecols, k-slice of 32 ----
        {
            const float* ap = hs_s + q * 32;
            float* pq = ps + q * 2048 + 4 * lane;
            #pragma unroll 2
            for (int b = 0; b < 16; b++) {
                const float* a = ap + b * HSP;
                float s0 = 0.f, s1 = 0.f, s2 = 0.f, s3 = 0.f;
                #pragma unroll
                for (int k = 0; k < 32; k += 4) {
                    float4 av = *(const float4*)(a + k);
                    s0 = fmaf(av.x, wreg[0][k + 0], s0);
                    s1 = fmaf(av.x, wreg[1][k + 0], s1);
                    s2 = fmaf(av.x, wreg[2][k + 0], s2);
                    s3 = fmaf(av.x, wreg[3][k + 0], s3);
                    s0 = fmaf(av.y, wreg[0][k + 1], s0);
                    s1 = fmaf(av.y, wreg[1][k + 1], s1);
                    s2 = fmaf(av.y, wreg[2][k + 1], s2);
                    s3 = fmaf(av.y, wreg[3][k + 1], s3);
                    s0 = fmaf(av.z, wreg[0][k + 2], s0);
                    s1 = fmaf(av.z, wreg[1][k + 2], s1);
                    s2 = fmaf(av.z, wreg[2][k + 2], s2);
                    s3 = fmaf(av.z, wreg[3][k + 2], s3);
                    s0 = fmaf(av.w, wreg[0][k + 3], s0);
                    s1 = fmaf(av.w, wreg[1][k + 3], s1);
                    s2 = fmaf(av.w, wreg[2][k + 3], s2);
                    s3 = fmaf(av.w, wreg[3][k + 3], s3);
                }
                *(float4*)(pq + b * 128) = make_float4(s0, s1, s2, s3);
            }
        }
        __syncthreads();

        // ---- pointwise: reduce 8 partials + xp; update c, write h ----
        {
            const float* xp_t = g_xp + (size_t)t * 256 * 1024;
            float* h_out = hs + (size_t)t * 65536;
            #pragma unroll
            for (int i = 0; i < 2; i++) {
                int u = 2 * tid + i;
                int b = u >> 5, j = u & 31;
                float gi = 0.f, gf = 0.f, gg = 0.f, go = 0.f;
                #pragma unroll
                for (int qq = 0; qq < 8; qq++) {
                    const float* p = ps + qq * 2048 + b * 128;
                    gi += p[j]; gf += p[32 + j]; gg += p[64 + j]; go += p[96 + j];
                }
                const float* xr = xp_t + (size_t)(b0 + b) * 1024 + h0 + j;
                gi += xr[0]; gf += xr[256]; gg += xr[512]; go += xr[768];
                float c = sigf(gf) * c_s[u] + sigf(gi) * tanhfast(gg);
                c_s[u] = c;
                h_out[(size_t)(b0 + b) * 256 + h0 + j] = sigf(go) * tanhfast(c);
            }
        }

        if (t < 76) {
            __threadfence();
            asm volatile("barrier.cluster.arrive.aligned;" ::: "memory");
        }
    }
}

// ---------------- FC head ----------------
__global__ __launch_bounds__(256) void fc_kernel(
    int stage, const float* __restrict__ W, const float* __restrict__ bias,
    float* __restrict__ dout) {
    __shared__ float As[32][33];
    __shared__ float Ws[32][33];
    const float* A; float* out; int K, N; int relu;
    if (stage == 0) { A = g_y0 + (size_t)76 * 65536; out = g_f1; K = 256; N = 512; relu = 1; }
    else if (stage == 1) { A = g_f1; out = g_f2; K = 512; N = 512; relu = 1; }
    else { A = g_f2; out = dout; K = 512; N = 256; relu = 0; }
    int n0 = blockIdx.x * 32, m0 = blockIdx.y * 32;
    int tid = threadIdx.x;
    int lrow = tid >> 3, lkq = tid & 7;
    int ty = tid >> 4, tx = tid & 15;
    float acc[2][2] = {{0.f, 0.f}, {0.f, 0.f}};
    for (int k0 = 0; k0 < K; k0 += 32) {
        __syncthreads();
        {
            float4 va = *(const float4*)&A[(size_t)(m0 + lrow) * K + k0 + 4 * lkq];
            As[lrow][4*lkq+0] = va.x; As[lrow][4*lkq+1] = va.y;
            As[lrow][4*lkq+2] = va.z; As[lrow][4*lkq+3] = va.w;
            float4 vw = *(const float4*)&W[(size_t)(n0 + lrow) * K + k0 + 4 * lkq];
            Ws[lrow][4*lkq+0] = vw.x; Ws[lrow][4*lkq+1] = vw.y;
            Ws[lrow][4*lkq+2] = vw.z; Ws[lrow][4*lkq+3] = vw.w;
        }
        __syncthreads();
        #pragma unroll
        for (int kk = 0; kk < 32; kk++) {
            float a0 = As[2*ty][kk], a1 = As[2*ty+1][kk];
            float w0 = Ws[2*tx][kk], w1 = Ws[2*tx+1][kk];
            acc[0][0] = fmaf(a0, w0, acc[0][0]);
            acc[0][1] = fmaf(a0, w1, acc[0][1]);
            acc[1][0] = fmaf(a1, w0, acc[1][0]);
            acc[1][1] = fmaf(a1, w1, acc[1][1]);
        }
    }
    #pragma unroll
    for (int i = 0; i < 2; i++) {
        #pragma unroll
        for (int j = 0; j < 2; j++) {
            int m = m0 + 2 * ty + i, n = n0 + 2 * tx + j;
            float v = acc[i][j] + bias[n];
            if (relu) v = fmaxf(v, 0.f);
            out[(size_t)m * N + n] = v;
        }
    }
}

// ---------------- launch ----------------
extern "C" void kernel_launch(void* const* d_in, const int* in_sizes, int n_in,
                              void* d_out, int out_size) {
    const float* x       = (const float*)d_in[0];
    const float* conv_w0 = (const float*)d_in[1];
    const float* conv_b0 = (const float*)d_in[2];
    const float* bn_g0   = (const float*)d_in[3];
    const float* bn_b0   = (const float*)d_in[4];
    const float* bn_m0   = (const float*)d_in[5];
    const float* bn_v0   = (const float*)d_in[6];
    const float* conv_w1 = (const float*)d_in[7];
    const float* conv_b1 = (const float*)d_in[8];
    const float* bn_g1   = (const float*)d_in[9];
    const float* bn_b1   = (const float*)d_in[10];
    const float* bn_m1   = (const float*)d_in[11];
    const float* bn_v1   = (const float*)d_in[12];
    const float* Wih0    = (const float*)d_in[13];
    const float* Whh0    = (const float*)d_in[14];
    const float* bih0    = (const float*)d_in[15];
    const float* bhh0    = (const float*)d_in[16];
    const float* Wih1    = (const float*)d_in[17];
    const float* Whh1    = (const float*)d_in[18];
    const float* bih1    = (const float*)d_in[19];
    const float* bhh1    = (const float*)d_in[20];
    const float* fc0_w   = (const float*)d_in[21];
    const float* fc0_b   = (const float*)d_in[22];
    const float* fc1_w   = (const float*)d_in[23];
    const float* fc1_b   = (const float*)d_in[24];
    const float* out_w   = (const float*)d_in[25];
    const float* out_b   = (const float*)d_in[26];
    float* out = (float*)d_out;

    cudaFuncSetAttribute(lstm_persist_kernel,
                         cudaFuncAttributeMaxDynamicSharedMemorySize, LSTM_SMEM);
    cudaFuncSetAttribute(conv1_kernel,
                         cudaFuncAttributeMaxDynamicSharedMemorySize, C1_SMEM);

    savgol_kernel<<<dim3(40, 256), 256>>>(x);
    conv0_kernel<<<dim3(5, 256), 256>>>(conv_w0, conv_b0, bn_g0, bn_b0, bn_m0, bn_v0);
    conv1_kernel<<<dim3(3, 256), 256, C1_SMEM>>>(conv_w1, conv_b1, bn_g1, bn_b1, bn_m1, bn_v1);

    gemm_xproj_kernel<<<dim3(8, 154), 256>>>(0, Wih0, bih0, bhh0);
    lstm_persist_kernel<<<128, 256, LSTM_SMEM>>>(0, Whh0);

    gemm_xproj_kernel<<<dim3(8, 154), 256>>>(1, Wih1, bih1, bhh1);
    lstm_persist_kernel<<<128, 256, LSTM_SMEM>>>(1, Whh1);

    fc_kernel<<<dim3(16, 8), 256>>>(0, fc0_w, fc0_b, out);
    fc_kernel<<<dim3(16, 8), 256>>>(1, fc1_w, fc1_b, out);
    fc_kernel<<<dim3(8, 8), 256>>>(2, out_w, out_b, out);
}

// round 8
// speedup vs baseline: 1.3528x; 1.3528x over previous
#include <cuda_runtime.h>
#include <math.h>

// ---------------- scratch (static __device__, allocation-free) ----------------
__device__ float g_sg [256 * 10000];        // savgol output
__device__ float g_y0 [256 * 64 * 624];     // conv block 0 out (b,c,p); reused as layer1 hs
__device__ float g_seq[77 * 256 * 128];     // conv block 1 out, (t,b,c)
__device__ float g_xp [77 * 256 * 1024];    // lstm input projection (t,b,4H), reused per layer
__device__ float g_hs0[77 * 256 * 256];     // layer0 hidden sequence (t,b,H)
__device__ float g_f1 [256 * 512];
__device__ float g_f2 [256 * 512];
__device__ unsigned g_cnt[8];               // per-batch-tile arrival counters

// SG(11,3) interior smoothing taps (symmetric): [-36,9,44,69,84,89,84,69,44,9,-36]/429
__constant__ float c_sg[11] = {
    -36.f/429.f, 9.f/429.f, 44.f/429.f, 69.f/429.f, 84.f/429.f, 89.f/429.f,
    84.f/429.f, 69.f/429.f, 44.f/429.f, 9.f/429.f, -36.f/429.f };

// ---------------- f32x2 packed-math helpers ----------------
__device__ __forceinline__ unsigned long long pk2(float a, float b) {
    unsigned long long r;
    asm("mov.b64 %0, {%1, %2};" : "=l"(r) : "f"(a), "f"(b));
    return r;
}
__device__ __forceinline__ void fma2(unsigned long long& d,
                                     unsigned long long a, unsigned long long b) {
    asm("fma.rn.f32x2 %0, %1, %2, %0;" : "+l"(d) : "l"(a), "l"(b));
}
__device__ __forceinline__ float2 upk(unsigned long long v) {
    float2 r;
    asm("mov.b64 {%0, %1}, %2;" : "=f"(r.x), "=f"(r.y) : "l"(v));
    return r;
}

__global__ void reset_cnt_kernel() {
    if (threadIdx.x < 8) g_cnt[threadIdx.x] = 0;
}

// ---------------- savgol ----------------
__device__ __forceinline__ void sg_fit(const float* __restrict__ xw, double a[4]) {
    double m0 = 0, m1 = 0, m2 = 0, m3 = 0;
    #pragma unroll
    for (int w = 0; w < 11; w++) {
        double y = (double)xw[w]; double t = (double)w;
        m0 += y; m1 += y * t; m2 += y * t * t; m3 += y * t * t * t;
    }
    double M[4][5] = {
        {11.0,    55.0,     385.0,     3025.0,    m0},
        {55.0,    385.0,    3025.0,    25333.0,   m1},
        {385.0,   3025.0,   25333.0,   220825.0,  m2},
        {3025.0,  25333.0,  220825.0,  1978405.0, m3}};
    #pragma unroll
    for (int i = 0; i < 4; i++) {
        double p = M[i][i];
        #pragma unroll
        for (int j = i; j < 5; j++) M[i][j] /= p;
        #pragma unroll
        for (int r = 0; r < 4; r++) {
            if (r != i) {
                double f = M[r][i];
                #pragma unroll
                for (int j = i; j < 5; j++) M[r][j] -= f * M[i][j];
            }
        }
    }
    a[0] = M[0][4]; a[1] = M[1][4]; a[2] = M[2][4]; a[3] = M[3][4];
}

__global__ __launch_bounds__(256) void savgol_kernel(const float* __restrict__ x) {
    int b = blockIdx.y;
    int i = blockIdx.x * 256 + threadIdx.x;
    if (i >= 10000) return;
    const float* xr = x + (size_t)b * 10000;
    float* o = g_sg + (size_t)b * 10000;
    if (i >= 5 && i < 9995) {
        float acc = 0.f;
        #pragma unroll
        for (int j = 0; j < 11; j++) acc = fmaf(xr[i - 5 + j], c_sg[j], acc);
        o[i] = acc;
    } else if (i < 5) {
        double a[4]; sg_fit(xr, a);
        double t = (double)i;
        o[i] = (float)(a[0] + t * (a[1] + t * (a[2] + t * a[3])));
    } else {
        double a[4]; sg_fit(xr + 9989, a);
        double t = (double)(i - 9989);
        o[i] = (float)(a[0] + t * (a[1] + t * (a[2] + t * a[3])));
    }
}

// ---------------- conv block 0 ----------------
__global__ __launch_bounds__(256) void conv0_kernel(
    const float* __restrict__ w, const float* __restrict__ bias,
    const float* __restrict__ bg, const float* __restrict__ bb,
    const float* __restrict__ bm, const float* __restrict__ bv) {
    __shared__ float in_s[2064];
    __shared__ float ws[64][17];
    __shared__ float scs[64], shs[64], bss[64];
    int b = blockIdx.y;
    int p0 = blockIdx.x * 128;
    int tid = threadIdx.x;
    int base = 16 * p0;
    for (int i = tid; i < 2064; i += 256) {
        int col = base + i;
        in_s[i] = (col < 10000) ? g_sg[(size_t)b * 10000 + col] : 0.f;
    }
    for (int i = tid; i < 1024; i += 256) ws[i >> 4][i & 15] = w[i];
    if (tid < 64) {
        float sc = bg[tid] * rsqrtf(bv[tid] + 1e-5f);
        scs[tid] = sc;
        shs[tid] = bb[tid] - bm[tid] * sc;
        bss[tid] = bias[tid];
    }
    __syncthreads();
    int p = p0 + (tid & 127);
    int cb = (tid >> 7) * 32;
    if (p >= 624) return;
    float xr[24];
    int lb = 16 * (tid & 127);
    #pragma unroll
    for (int k = 0; k < 24; k++) xr[k] = in_s[lb + k];
    #pragma unroll 4
    for (int c = cb; c < cb + 32; c++) {
        float s1 = 0.f, s2 = 0.f;
        #pragma unroll
        for (int k = 0; k < 16; k++) {
            float wv = ws[c][k];
            s1 = fmaf(wv, xr[k], s1);
            s2 = fmaf(wv, xr[k + 8], s2);
        }
        float m = fmaxf(fmaxf(s1, s2) + bss[c], 0.f);
        g_y0[((size_t)b * 64 + c) * 624 + p] = scs[c] * m + shs[c];
    }
}

// ---------------- conv block 1 (v3: 8oc x 4pos microtile, 32 pooled/CTA) ----------------
#define C1_IN   (64 * 260)
#define C1_WS   (4 * 8 * 128)
#define C1_SMEM ((C1_IN + C1_WS + 3 * 128) * 4)

__global__ __launch_bounds__(256) void conv1_kernel(
    const float* __restrict__ w, const float* __restrict__ bias,
    const float* __restrict__ bg, const float* __restrict__ bb,
    const float* __restrict__ bm, const float* __restrict__ bv) {
    extern __shared__ float c1s[];
    float* in_s = c1s;                       // [64][260]
    float* ws   = c1s + C1_IN;               // [4][8][128]
    float* scs  = ws + C1_WS;
    float* shs  = scs + 128;
    float* bss  = shs + 128;

    int b = blockIdx.y;
    int p0 = blockIdx.x * 32;
    int tid = threadIdx.x;
    int cg = tid & 15, pg = tid >> 4;        // 8 oc per cg, 2 pooled per pg

    for (int i = tid; i < C1_IN; i += 256) {
        int ic = i / 260, cc = i % 260;
        int col = 8 * p0 + cc;
        in_s[i] = (col < 624) ? g_y0[((size_t)b * 64 + ic) * 624 + col] : 0.f;
    }
    if (tid < 128) {
        float sc = bg[tid] * rsqrtf(bv[tid] + 1e-5f);
        scs[tid] = sc;
        shs[tid] = bb[tid] - bm[tid] * sc;
        bss[tid] = bias[tid];
    }
    float acc[8][4];
    #pragma unroll
    for (int i = 0; i < 8; i++)
        #pragma unroll
        for (int j = 0; j < 4; j++) acc[i][j] = 0.f;

    int ocl = tid & 127, half = tid >> 7;
    for (int ic0 = 0; ic0 < 64; ic0 += 4) {
        __syncthreads();
        #pragma unroll
        for (int il = 0; il < 2; il++) {
            int icl = half * 2 + il;
            const float4* src = (const float4*)(w + ((size_t)ocl * 64 + ic0 + icl) * 8);
            float4 v0 = src[0], v1 = src[1];
            float* wd = ws + icl * 1024 + ocl;
            wd[0 * 128] = v0.x; wd[1 * 128] = v0.y; wd[2 * 128] = v0.z; wd[3 * 128] = v0.w;
            wd[4 * 128] = v1.x; wd[5 * 128] = v1.y; wd[6 * 128] = v1.z; wd[7 * 128] = v1.w;
        }
        __syncthreads();
        #pragma unroll
        for (int icl = 0; icl < 4; icl++) {
            #pragma unroll
            for (int t = 0; t < 8; t++) {
                float4 wa = *(const float4*)&ws[icl * 1024 + t * 128 + cg * 8];
                float4 wb = *(const float4*)&ws[icl * 1024 + t * 128 + cg * 8 + 4];
                const float* ir = in_s + (ic0 + icl) * 260 + 16 * pg + t;
                #pragma unroll
                for (int qc = 0; qc < 4; qc++) {
                    float iv = ir[4 * qc];
                    acc[0][qc] = fmaf(wa.x, iv, acc[0][qc]);
                    acc[1][qc] = fmaf(wa.y, iv, acc[1][qc]);
                    acc[2][qc] = fmaf(wa.z, iv, acc[2][qc]);
                    acc[3][qc] = fmaf(wa.w, iv, acc[3][qc]);
                    acc[4][qc] = fmaf(wb.x, iv, acc[4][qc]);
                    acc[5][qc] = fmaf(wb.y, iv, acc[5][qc]);
                    acc[6][qc] = fmaf(wb.z, iv, acc[6][qc]);
                    acc[7][qc] = fmaf(wb.w, iv, acc[7][qc]);
                }
            }
        }
    }
    #pragma unroll
    for (int pp = 0; pp < 2; pp++) {
        int p = p0 + 2 * pg + pp;
        if (p >= 77) continue;
        float ov[8];
        #pragma unroll
        for (int i = 0; i < 8; i++) {
            int oc = 8 * cg + i;
            float m = fmaxf(acc[i][2 * pp], acc[i][2 * pp + 1]);
            float v = fmaxf(m + bss[oc], 0.f);
            ov[i] = scs[oc] * v + shs[oc];
        }
        float* dst = &g_seq[((size_t)p * 256 + b) * 128 + 8 * cg];
        *(float4*)dst = make_float4(ov[0], ov[1], ov[2], ov[3]);
        *(float4*)(dst + 4) = make_float4(ov[4], ov[5], ov[6], ov[7]);
    }
}

// ---------------- input-projection GEMM (f32x2): g_xp = A @ Wih^T + (bih+bhh) ----------------
__global__ __launch_bounds__(256) void gemm_xproj_kernel(
    int src, const float* __restrict__ Wih,
    const float* __restrict__ b1, const float* __restrict__ b2) {
    __shared__ float As[16][132];
    __shared__ float Ws[16][132];
    const int K = src ? 256 : 128;
    const float* A = src ? g_hs0 : g_seq;
    int n0 = blockIdx.x * 128, m0 = blockIdx.y * 128;
    int tid = threadIdx.x;
    int lr = tid >> 2, lq = tid & 3;
    int tx = tid & 15, ty = tid >> 4;
    unsigned long long acc2[8][4];
    #pragma unroll
    for (int i = 0; i < 8; i++)
        #pragma unroll
        for (int j = 0; j < 4; j++) acc2[i][j] = 0ull;

    const float* a0p = A + (size_t)(m0 + lr) * K + 4 * lq;
    const float* a1p = A + (size_t)(m0 + lr + 64) * K + 4 * lq;
    const float* w0p = Wih + (size_t)(n0 + lr) * K + 4 * lq;
    const float* w1p = Wih + (size_t)(n0 + lr + 64) * K + 4 * lq;

    float4 pa0 = *(const float4*)a0p;
    float4 pa1 = *(const float4*)a1p;
    float4 pw0 = *(const float4*)w0p;
    float4 pw1 = *(const float4*)w1p;

    int nch = K >> 4;
    for (int c = 0; c < nch; c++) {
        As[4*lq+0][lr] = pa0.x; As[4*lq+1][lr] = pa0.y; As[4*lq+2][lr] = pa0.z; As[4*lq+3][lr] = pa0.w;
        As[4*lq+0][lr+64] = pa1.x; As[4*lq+1][lr+64] = pa1.y; As[4*lq+2][lr+64] = pa1.z; As[4*lq+3][lr+64] = pa1.w;
        Ws[4*lq+0][lr] = pw0.x; Ws[4*lq+1][lr] = pw0.y; Ws[4*lq+2][lr] = pw0.z; Ws[4*lq+3][lr] = pw0.w;
        Ws[4*lq+0][lr+64] = pw1.x; Ws[4*lq+1][lr+64] = pw1.y; Ws[4*lq+2][lr+64] = pw1.z; Ws[4*lq+3][lr+64] = pw1.w;
        __syncthreads();
        if (c + 1 < nch) {
            int k0 = (c + 1) * 16;
            pa0 = *(const float4*)(a0p + k0);
            pa1 = *(const float4*)(a1p + k0);
            pw0 = *(const float4*)(w0p + k0);
            pw1 = *(const float4*)(w1p + k0);
        }
        #pragma unroll
        for (int kk = 0; kk < 16; kk++) {
            float a[8];
            *(float4*)&a[0] = *(const float4*)&As[kk][8 * ty];
            *(float4*)&a[4] = *(const float4*)&As[kk][8 * ty + 4];
            ulonglong2 bA = *(const ulonglong2*)&Ws[kk][8 * tx];
            ulonglong2 bB = *(const ulonglong2*)&Ws[kk][8 * tx + 4];
            #pragma unroll
            for (int i = 0; i < 8; i++) {
                unsigned long long ad = pk2(a[i], a[i]);
                fma2(acc2[i][0], ad, bA.x);
                fma2(acc2[i][1], ad, bA.y);
                fma2(acc2[i][2], ad, bB.x);
                fma2(acc2[i][3], ad, bB.y);
            }
        }
        __syncthreads();
    }
    float bv[8];
    #pragma unroll
    for (int j = 0; j < 8; j++) {
        int n = n0 + 8 * tx + j;
        bv[j] = b1[n] + b2[n];
    }
    #pragma unroll
    for (int i = 0; i < 8; i++) {
        size_t row = (size_t)(m0 + 8 * ty + i) * 1024 + n0 + 8 * tx;
        float2 p0 = upk(acc2[i][0]), p1 = upk(acc2[i][1]);
        float2 p2 = upk(acc2[i][2]), p3 = upk(acc2[i][3]);
        float4 o0 = make_float4(p0.x + bv[0], p0.y + bv[1], p1.x + bv[2], p1.y + bv[3]);
        float4 o1 = make_float4(p2.x + bv[4], p2.y + bv[5], p3.x + bv[6], p3.y + bv[7]);
        *(float4*)&g_xp[row]     = o0;
        *(float4*)&g_xp[row + 4] = o1;
    }
}

// ---------------- persistent LSTM layer (v6: f32x2 GEMM, k-major h tile) ----------------
// 128 CTAs (8 bt x 16 ht) x 256 threads, 1/SM.
// CTA tile: 32 batch x 64 gatecols (16 hidden x 4 gates), K=256.
// Warp q = k-slice [32q,+32); lane owns gatecols {2*lane, 2*lane+1} with Whh
// DUPLICATE-PACKED (w,w) in 64 b64 regs. h_prev in smem k-major [256][36]:
// one 16B LDS gives batches (b..b+3) as two natural f32x2 operands.
// Inner: 1 LDS.128 + 4 FFMA2 per (k, 4 batches). Partials ps2[q][bpair][gc][2].
#define HSK 36
#define PS2_OFF (256 * HSK)
#define CS_OFF2 (PS2_OFF + 8 * 16 * 64 * 2)
#define LSTM_SMEM ((256 * HSK + 8 * 16 * 64 * 2 + 512) * 4)

__device__ __forceinline__ float sigf(float x) {
    return __fdividef(1.f, 1.f + __expf(-x));
}
__device__ __forceinline__ float tanhfast(float x) {
    return 2.f * sigf(2.f * x) - 1.f;
}

__global__ __launch_bounds__(256) void lstm_persist_kernel(
    int layer, unsigned base, const float* __restrict__ Whh) {
    extern __shared__ float sm[];
    float* hs_s = sm;                 // [256][HSK] k-major h_prev tile
    float* ps2  = sm + PS2_OFF;       // [8][16][64][2] split-K partials
    float* c_s  = sm + CS_OFF2;       // [512] cell state

    int tid = threadIdx.x;
    int q = tid >> 5;                 // warp = k-slice
    int lane = tid & 31;
    int bt = blockIdx.x >> 4, ht = blockIdx.x & 15;
    int b0 = bt * 32, h0 = ht * 16;
    float* hs = layer ? g_y0 : g_hs0;

    // ---- Whh slice, duplicate-packed (once per launch) ----
    unsigned long long wd0[32], wd1[32];
    {
        int gc0 = 2 * lane, gc1 = 2 * lane + 1;
        const float* r0 = Whh + (size_t)((gc0 >> 4) * 256 + h0 + (gc0 & 15)) * 256 + q * 32;
        const float* r1 = Whh + (size_t)((gc1 >> 4) * 256 + h0 + (gc1 & 15)) * 256 + q * 32;
        #pragma unroll
        for (int k = 0; k < 32; k++) {
            float w0 = r0[k], w1 = r1[k];
            wd0[k] = pk2(w0, w0);
            wd1[k] = pk2(w1, w1);
        }
    }
    c_s[2 * tid] = 0.f;
    c_s[2 * tid + 1] = 0.f;
    unsigned* cnt = &g_cnt[bt];

    // stage mapping: thread = (batch sb, k-quarter skq of 32 k)
    int sb = tid & 31;
    int skq = tid >> 5;
    // pointwise mapping
    int ub0 = (2 * tid) >> 4, uj0 = (2 * tid) & 15;
    int ub1 = (2 * tid + 1) >> 4, uj1 = (2 * tid + 1) & 15;

    for (int t = 0; t < 77; t++) {
        // ---- prefetch xp for this step (independent of the barrier) ----
        const float* xp_t = g_xp + (size_t)t * 262144;
        const float* xr0 = xp_t + (size_t)(b0 + ub0) * 1024 + h0 + uj0;
        const float* xr1 = xp_t + (size_t)(b0 + ub1) * 1024 + h0 + uj1;
        float xi0 = xr0[0], xf0 = xr0[256], xg0 = xr0[512], xo0 = xr0[768];
        float xi1 = xr1[0], xf1 = xr1[256], xg1 = xr1[512], xo1 = xr1[768];

        // ---- wait for h(t-1) ----
        if (t > 0) {
            if (tid == 0) {
                unsigned target = base + 16u * (unsigned)t;
                while (*(volatile unsigned*)cnt < target) { }
                __threadfence();
            }
            __syncthreads();
        }

        // ---- stage h_prev into k-major tile ----
        if (t == 0) {
            #pragma unroll
            for (int i = 0; i < 32; i++)
                hs_s[(skq * 32 + i) * HSK + sb] = 0.f;
        } else {
            const float* srcp = hs + (size_t)(t - 1) * 65536 + (size_t)(b0 + sb) * 256 + skq * 32;
            #pragma unroll
            for (int i = 0; i < 32; i += 4) {
                float4 v = *(const float4*)&srcp[i];
                hs_s[(skq * 32 + i + 0) * HSK + sb] = v.x;
                hs_s[(skq * 32 + i + 1) * HSK + sb] = v.y;
                hs_s[(skq * 32 + i + 2) * HSK + sb] = v.z;
                hs_s[(skq * 32 + i + 3) * HSK + sb] = v.w;
            }
        }
        __syncthreads();

        // ---- split-K GEMM (f32x2): 8 groups of 4 batches ----
        {
            const float* apb = hs_s + (q * 32) * HSK;
            float* myps = ps2 + q * 2048;           // [16][64][2]
            int gc0 = 2 * lane, gc1 = 2 * lane + 1;
            #pragma unroll
            for (int grp = 0; grp < 8; grp++) {
                unsigned long long aA0 = 0ull, aA1 = 0ull, aB0 = 0ull, aB1 = 0ull;
                const float* ap = apb + grp * 4;
                #pragma unroll
                for (int k = 0; k < 32; k++) {
                    ulonglong2 av = *(const ulonglong2*)(ap + k * HSK);
                    fma2(aA0, av.x, wd0[k]);
                    fma2(aA1, av.y, wd0[k]);
                    fma2(aB0, av.x, wd1[k]);
                    fma2(aB1, av.y, wd1[k]);
                }
                int p0i = grp * 2, p1i = grp * 2 + 1;
                *(unsigned long long*)&myps[(p0i * 64 + gc0) * 2] = aA0;
                *(unsigned long long*)&myps[(p1i * 64 + gc0) * 2] = aA1;
                *(unsigned long long*)&myps[(p0i * 64 + gc1) * 2] = aB0;
                *(unsigned long long*)&myps[(p1i * 64 + gc1) * 2] = aB1;
            }
        }
        __syncthreads();

        // ---- pointwise: reduce 8 partials + prefetched xp; update c, write h ----
        {
            float* h_out = hs + (size_t)t * 65536;
            // unit 0
            {
                int b = ub0, j = uj0, u = 2 * tid;
                int bp = (b >> 1), sel = (b & 1);
                float gi = xi0, gf = xf0, gg = xg0, go = xo0;
                #pragma unroll
                for (int qq = 0; qq < 8; qq++) {
                    const float* p = ps2 + qq * 2048 + (bp * 64) * 2 + sel;
                    gi += p[(j) * 2];
                    gf += p[(16 + j) * 2];
                    gg += p[(32 + j) * 2];
                    go += p[(48 + j) * 2];
                }
                float c = sigf(gf) * c_s[u] + sigf(gi) * tanhfast(gg);
                c_s[u] = c;
                h_out[(size_t)(b0 + b) * 256 + h0 + j] = sigf(go) * tanhfast(c);
            }
            // unit 1
            {
                int b = ub1, j = uj1, u = 2 * tid + 1;
                int bp = (b >> 1), sel = (b & 1);
                float gi = xi1, gf = xf1, gg = xg1, go = xo1;
                #pragma unroll
                for (int qq = 0; qq < 8; qq++) {
                    const float* p = ps2 + qq * 2048 + (bp * 64) * 2 + sel;
                    gi += p[(j) * 2];
                    gf += p[(16 + j) * 2];
                    gg += p[(32 + j) * 2];
                    go += p[(48 + j) * 2];
                }
                float c = sigf(gf) * c_s[u] + sigf(gi) * tanhfast(gg);
                c_s[u] = c;
                h_out[(size_t)(b0 + b) * 256 + h0 + j] = sigf(go) * tanhfast(c);
            }
        }

        // ---- arrive ----
        if (t < 76) {
            __syncthreads();
            if (tid == 0) {
                __threadfence();
                atomicAdd(cnt, 1u);
            }
        }
    }
}

// ---------------- FC head ----------------
__global__ __launch_bounds__(256) void fc_kernel(
    int stage, const float* __restrict__ W, const float* __restrict__ bias,
    float* __restrict__ dout) {
    __shared__ float As[32][33];
    __shared__ float Ws[32][33];
    const float* A; float* out; int K, N; int relu;
    if (stage == 0) { A = g_y0 + (size_t)76 * 65536; out = g_f1; K = 256; N = 512; relu = 1; }
    else if (stage == 1) { A = g_f1; out = g_f2; K = 512; N = 512; relu = 1; }
    else { A = g_f2; out = dout; K = 512; N = 256; relu = 0; }
    int n0 = blockIdx.x * 32, m0 = blockIdx.y * 32;
    int tid = threadIdx.x;
    int lrow = tid >> 3, lkq = tid & 7;
    int ty = tid >> 4, tx = tid & 15;
    float acc[2][2] = {{0.f, 0.f}, {0.f, 0.f}};
    for (int k0 = 0; k0 < K; k0 += 32) {
        __syncthreads();
        {
            float4 va = *(const float4*)&A[(size_t)(m0 + lrow) * K + k0 + 4 * lkq];
            As[lrow][4*lkq+0] = va.x; As[lrow][4*lkq+1] = va.y;
            As[lrow][4*lkq+2] = va.z; As[lrow][4*lkq+3] = va.w;
            float4 vw = *(const float4*)&W[(size_t)(n0 + lrow) * K + k0 + 4 * lkq];
            Ws[lrow][4*lkq+0] = vw.x; Ws[lrow][4*lkq+1] = vw.y;
            Ws[lrow][4*lkq+2] = vw.z; Ws[lrow][4*lkq+3] = vw.w;
        }
        __syncthreads();
        #pragma unroll
        for (int kk = 0; kk < 32; kk++) {
            float a0 = As[2*ty][kk], a1 = As[2*ty+1][kk];
            float w0 = Ws[2*tx][kk], w1 = Ws[2*tx+1][kk];
            acc[0][0] = fmaf(a0, w0, acc[0][0]);
            acc[0][1] = fmaf(a0, w1, acc[0][1]);
            acc[1][0] = fmaf(a1, w0, acc[1][0]);
            acc[1][1] = fmaf(a1, w1, acc[1][1]);
        }
    }
    #pragma unroll
    for (int i = 0; i < 2; i++) {
        #pragma unroll
        for (int j = 0; j < 2; j++) {
            int m = m0 + 2 * ty + i, n = n0 + 2 * tx + j;
            float v = acc[i][j] + bias[n];
            if (relu) v = fmaxf(v, 0.f);
            out[(size_t)m * N + n] = v;
        }
    }
}

// ---------------- launch ----------------
extern "C" void kernel_launch(void* const* d_in, const int* in_sizes, int n_in,
                              void* d_out, int out_size) {
    const float* x       = (const float*)d_in[0];
    const float* conv_w0 = (const float*)d_in[1];
    const float* conv_b0 = (const float*)d_in[2];
    const float* bn_g0   = (const float*)d_in[3];
    const float* bn_b0   = (const float*)d_in[4];
    const float* bn_m0   = (const float*)d_in[5];
    const float* bn_v0   = (const float*)d_in[6];
    const float* conv_w1 = (const float*)d_in[7];
    const float* conv_b1 = (const float*)d_in[8];
    const float* bn_g1   = (const float*)d_in[9];
    const float* bn_b1   = (const float*)d_in[10];
    const float* bn_m1   = (const float*)d_in[11];
    const float* bn_v1   = (const float*)d_in[12];
    const float* Wih0    = (const float*)d_in[13];
    const float* Whh0    = (const float*)d_in[14];
    const float* bih0    = (const float*)d_in[15];
    const float* bhh0    = (const float*)d_in[16];
    const float* Wih1    = (const float*)d_in[17];
    const float* Whh1    = (const float*)d_in[18];
    const float* bih1    = (const float*)d_in[19];
    const float* bhh1    = (const float*)d_in[20];
    const float* fc0_w   = (const float*)d_in[21];
    const float* fc0_b   = (const float*)d_in[22];
    const float* fc1_w   = (const float*)d_in[23];
    const float* fc1_b   = (const float*)d_in[24];
    const float* out_w   = (const float*)d_in[25];
    const float* out_b   = (const float*)d_in[26];
    float* out = (float*)d_out;

    cudaFuncSetAttribute(lstm_persist_kernel,
                         cudaFuncAttributeMaxDynamicSharedMemorySize, LSTM_SMEM);
    cudaFuncSetAttribute(conv1_kernel,
                         cudaFuncAttributeMaxDynamicSharedMemorySize, C1_SMEM);

    reset_cnt_kernel<<<1, 32>>>();
    savgol_kernel<<<dim3(40, 256), 256>>>(x);
    conv0_kernel<<<dim3(5, 256), 256>>>(conv_w0, conv_b0, bn_g0, bn_b0, bn_m0, bn_v0);
    conv1_kernel<<<dim3(3, 256), 256, C1_SMEM>>>(conv_w1, conv_b1, bn_g1, bn_b1, bn_m1, bn_v1);

    gemm_xproj_kernel<<<dim3(8, 154), 256>>>(0, Wih0, bih0, bhh0);
    lstm_persist_kernel<<<128, 256, LSTM_SMEM>>>(0, 0u, Whh0);

    gemm_xproj_kernel<<<dim3(8, 154), 256>>>(1, Wih1, bih1, bhh1);
    lstm_persist_kernel<<<128, 256, LSTM_SMEM>>>(1, 16u * 76u, Whh1);

    fc_kernel<<<dim3(16, 8), 256>>>(0, fc0_w, fc0_b, out);
    fc_kernel<<<dim3(16, 8), 256>>>(1, fc1_w, fc1_b, out);
    fc_kernel<<<dim3(8, 8), 256>>>(2, out_w, out_b, out);
}

// round 9
// speedup vs baseline: 1.3833x; 1.0226x over previous
#include <cuda_runtime.h>
#include <math.h>

// ---------------- scratch (static __device__, allocation-free) ----------------
__device__ float g_y0 [256 * 64 * 624];     // conv block 0 out (b,c,p); reused as layer1 hs
__device__ float g_seq[77 * 256 * 128];     // conv block 1 out, (t,b,c)
__device__ float g_xp [77 * 256 * 1024];    // lstm input projection (t,b,4H), reused per layer
__device__ float g_hs0[77 * 256 * 256];     // layer0 hidden sequence (t,b,H)
__device__ float g_f1 [256 * 512];
__device__ float g_f2 [256 * 512];
__device__ unsigned g_cnt[8];               // per-batch-tile arrival counters

// SG(11,3) interior smoothing taps (symmetric): [-36,9,44,69,84,89,84,69,44,9,-36]/429
__constant__ float c_sg[11] = {
    -36.f/429.f, 9.f/429.f, 44.f/429.f, 69.f/429.f, 84.f/429.f, 89.f/429.f,
    84.f/429.f, 69.f/429.f, 44.f/429.f, 9.f/429.f, -36.f/429.f };

// ---------------- f32x2 packed-math helpers ----------------
__device__ __forceinline__ unsigned long long pk2(float a, float b) {
    unsigned long long r;
    asm("mov.b64 %0, {%1, %2};" : "=l"(r) : "f"(a), "f"(b));
    return r;
}
__device__ __forceinline__ void fma2(unsigned long long& d,
                                     unsigned long long a, unsigned long long b) {
    asm("fma.rn.f32x2 %0, %1, %2, %0;" : "+l"(d) : "l"(a), "l"(b));
}
__device__ __forceinline__ float2 upk(unsigned long long v) {
    float2 r;
    asm("mov.b64 {%0, %1}, %2;" : "=f"(r.x), "=f"(r.y) : "l"(v));
    return r;
}

__global__ void reset_cnt_kernel() {
    if (threadIdx.x < 8) g_cnt[threadIdx.x] = 0;
}

// ---------------- savgol edge fit (cols 0..4 only; high edge is never consumed) ----------------
__device__ __forceinline__ void sg_fit(const float* __restrict__ xw, double a[4]) {
    double m0 = 0, m1 = 0, m2 = 0, m3 = 0;
    #pragma unroll
    for (int w = 0; w < 11; w++) {
        double y = (double)xw[w]; double t = (double)w;
        m0 += y; m1 += y * t; m2 += y * t * t; m3 += y * t * t * t;
    }
    double M[4][5] = {
        {11.0,    55.0,     385.0,     3025.0,    m0},
        {55.0,    385.0,    3025.0,    25333.0,   m1},
        {385.0,   3025.0,   25333.0,   220825.0,  m2},
        {3025.0,  25333.0,  220825.0,  1978405.0, m3}};
    #pragma unroll
    for (int i = 0; i < 4; i++) {
        double p = M[i][i];
        #pragma unroll
        for (int j = i; j < 5; j++) M[i][j] /= p;
        #pragma unroll
        for (int r = 0; r < 4; r++) {
            if (r != i) {
                double f = M[r][i];
                #pragma unroll
                for (int j = i; j < 5; j++) M[r][j] -= f * M[i][j];
            }
        }
    }
    a[0] = M[0][4]; a[1] = M[1][4]; a[2] = M[2][4]; a[3] = M[3][4];
}

// ---------------- conv block 0 (savgol fused in) ----------------
// grid (5, 256): 128 pooled positions per block. base = 2048*bx.
// Stage raw x[base-5 .. base+2068], FIR -> in_s[2064], then conv+pool+BN.
__global__ __launch_bounds__(256) void conv0_kernel(
    const float* __restrict__ x,
    const float* __restrict__ w, const float* __restrict__ bias,
    const float* __restrict__ bg, const float* __restrict__ bb,
    const float* __restrict__ bm, const float* __restrict__ bv) {
    __shared__ float xs[2080];
    __shared__ float in_s[2064];
    __shared__ float ws[64][17];
    __shared__ float scs[64], shs[64], bss[64];
    int b = blockIdx.y;
    int p0 = blockIdx.x * 128;
    int tid = threadIdx.x;
    int base = 16 * p0;
    const float* xr = x + (size_t)b * 10000;
    for (int i = tid; i < 2074; i += 256) {
        int col = base - 5 + i;
        xs[i] = (col >= 0 && col < 10000) ? xr[col] : 0.f;
    }
    for (int i = tid; i < 1024; i += 256) ws[i >> 4][i & 15] = w[i];
    if (tid < 64) {
        float sc = bg[tid] * rsqrtf(bv[tid] + 1e-5f);
        scs[tid] = sc;
        shs[tid] = bb[tid] - bm[tid] * sc;
        bss[tid] = bias[tid];
    }
    __syncthreads();
    // savgol FIR (interior); low-edge cols 0..4 patched below
    for (int i = tid; i < 2064; i += 256) {
        float acc = 0.f;
        #pragma unroll
        for (int j = 0; j < 11; j++) acc = fmaf(xs[i + j], c_sg[j], acc);
        in_s[i] = acc;
    }
    if (blockIdx.x == 0 && tid < 5) {
        double a[4]; sg_fit(xs + 5, a);   // xs[5..15] = x[0..10]
        double t = (double)tid;
        in_s[tid] = (float)(a[0] + t * (a[1] + t * (a[2] + t * a[3])));
    }
    __syncthreads();
    int p = p0 + (tid & 127);
    int cb = (tid >> 7) * 32;
    if (p >= 624) return;
    float xv[24];
    int lb = 16 * (tid & 127);
    #pragma unroll
    for (int k = 0; k < 24; k++) xv[k] = in_s[lb + k];
    #pragma unroll 4
    for (int c = cb; c < cb + 32; c++) {
        float s1 = 0.f, s2 = 0.f;
        #pragma unroll
        for (int k = 0; k < 16; k++) {
            float wv = ws[c][k];
            s1 = fmaf(wv, xv[k], s1);
            s2 = fmaf(wv, xv[k + 8], s2);
        }
        float m = fmaxf(fmaxf(s1, s2) + bss[c], 0.f);
        g_y0[((size_t)b * 64 + c) * 624 + p] = scs[c] * m + shs[c];
    }
}

// ---------------- conv block 1 (R6 version: 16 pooled/CTA, 4oc x 4pos) ----------------
#define C1_IN   (64 * 132)
#define C1_WS   (4 * 8 * 128)
#define C1_SMEM ((C1_IN + C1_WS + 3 * 128) * 4)

__global__ __launch_bounds__(256) void conv1_kernel(
    const float* __restrict__ w, const float* __restrict__ bias,
    const float* __restrict__ bg, const float* __restrict__ bb,
    const float* __restrict__ bm, const float* __restrict__ bv) {
    extern __shared__ float c1s[];
    float* in_s = c1s;                       // [64][132]
    float* ws   = c1s + C1_IN;               // [4][8][128]
    float* scs  = ws + C1_WS;
    float* shs  = scs + 128;
    float* bss  = shs + 128;

    int b = blockIdx.y;
    int p0 = blockIdx.x * 16;
    int tid = threadIdx.x;
    int cg = tid & 31, pg = tid >> 5;

    for (int i = tid; i < C1_IN; i += 256) {
        int ic = i / 132, cc = i % 132;
        int col = 8 * p0 + cc;
        in_s[i] = (col < 624) ? g_y0[((size_t)b * 64 + ic) * 624 + col] : 0.f;
    }
    if (tid < 128) {
        float sc = bg[tid] * rsqrtf(bv[tid] + 1e-5f);
        scs[tid] = sc;
        shs[tid] = bb[tid] - bm[tid] * sc;
        bss[tid] = bias[tid];
    }
    float acc[4][4];
    #pragma unroll
    for (int i = 0; i < 4; i++)
        #pragma unroll
        for (int j = 0; j < 4; j++) acc[i][j] = 0.f;

    int ocl = tid & 127, half = tid >> 7;
    for (int ic0 = 0; ic0 < 64; ic0 += 4) {
        __syncthreads();
        #pragma unroll
        for (int il = 0; il < 2; il++) {
            int icl = half * 2 + il;
            const float4* src = (const float4*)(w + ((size_t)ocl * 64 + ic0 + icl) * 8);
            float4 v0 = src[0], v1 = src[1];
            float* wd = ws + icl * 1024 + ocl;
            wd[0 * 128] = v0.x; wd[1 * 128] = v0.y; wd[2 * 128] = v0.z; wd[3 * 128] = v0.w;
            wd[4 * 128] = v1.x; wd[5 * 128] = v1.y; wd[6 * 128] = v1.z; wd[7 * 128] = v1.w;
        }
        __syncthreads();
        #pragma unroll
        for (int icl = 0; icl < 4; icl++) {
            #pragma unroll
            for (int t = 0; t < 8; t++) {
                float4 w4 = *(const float4*)&ws[icl * 1024 + t * 128 + cg * 4];
                const float* ir = in_s + (ic0 + icl) * 132 + 16 * pg + t;
                #pragma unroll
                for (int qc = 0; qc < 4; qc++) {
                    float iv = ir[4 * qc];
                    acc[0][qc] = fmaf(w4.x, iv, acc[0][qc]);
                    acc[1][qc] = fmaf(w4.y, iv, acc[1][qc]);
                    acc[2][qc] = fmaf(w4.z, iv, acc[2][qc]);
                    acc[3][qc] = fmaf(w4.w, iv, acc[3][qc]);
                }
            }
        }
    }
    #pragma unroll
    for (int pp = 0; pp < 2; pp++) {
        int p = p0 + 2 * pg + pp;
        if (p >= 77) continue;
        float ov[4];
        #pragma unroll
        for (int i = 0; i < 4; i++) {
            int oc = 4 * cg + i;
            float m = fmaxf(acc[i][2 * pp], acc[i][2 * pp + 1]);
            float v = fmaxf(m + bss[oc], 0.f);
            ov[i] = scs[oc] * v + shs[oc];
        }
        *(float4*)&g_seq[((size_t)p * 256 + b) * 128 + 4 * cg] =
            make_float4(ov[0], ov[1], ov[2], ov[3]);
    }
}

// ---------------- input-projection GEMM (f32x2): g_xp = A @ Wih^T + (bih+bhh) ----------------
__global__ __launch_bounds__(256) void gemm_xproj_kernel(
    int src, const float* __restrict__ Wih,
    const float* __restrict__ b1, const float* __restrict__ b2) {
    __shared__ float As[16][132];
    __shared__ float Ws[16][132];
    const int K = src ? 256 : 128;
    const float* A = src ? g_hs0 : g_seq;
    int n0 = blockIdx.x * 128, m0 = blockIdx.y * 128;
    int tid = threadIdx.x;
    int lr = tid >> 2, lq = tid & 3;
    int tx = tid & 15, ty = tid >> 4;
    unsigned long long acc2[8][4];
    #pragma unroll
    for (int i = 0; i < 8; i++)
        #pragma unroll
        for (int j = 0; j < 4; j++) acc2[i][j] = 0ull;

    const float* a0p = A + (size_t)(m0 + lr) * K + 4 * lq;
    const float* a1p = A + (size_t)(m0 + lr + 64) * K + 4 * lq;
    const float* w0p = Wih + (size_t)(n0 + lr) * K + 4 * lq;
    const float* w1p = Wih + (size_t)(n0 + lr + 64) * K + 4 * lq;

    float4 pa0 = *(const float4*)a0p;
    float4 pa1 = *(const float4*)a1p;
    float4 pw0 = *(const float4*)w0p;
    float4 pw1 = *(const float4*)w1p;

    int nch = K >> 4;
    for (int c = 0; c < nch; c++) {
        As[4*lq+0][lr] = pa0.x; As[4*lq+1][lr] = pa0.y; As[4*lq+2][lr] = pa0.z; As[4*lq+3][lr] = pa0.w;
        As[4*lq+0][lr+64] = pa1.x; As[4*lq+1][lr+64] = pa1.y; As[4*lq+2][lr+64] = pa1.z; As[4*lq+3][lr+64] = pa1.w;
        Ws[4*lq+0][lr] = pw0.x; Ws[4*lq+1][lr] = pw0.y; Ws[4*lq+2][lr] = pw0.z; Ws[4*lq+3][lr] = pw0.w;
        Ws[4*lq+0][lr+64] = pw1.x; Ws[4*lq+1][lr+64] = pw1.y; Ws[4*lq+2][lr+64] = pw1.z; Ws[4*lq+3][lr+64] = pw1.w;
        __syncthreads();
        if (c + 1 < nch) {
            int k0 = (c + 1) * 16;
            pa0 = *(const float4*)(a0p + k0);
            pa1 = *(const float4*)(a1p + k0);
            pw0 = *(const float4*)(w0p + k0);
            pw1 = *(const float4*)(w1p + k0);
        }
        #pragma unroll
        for (int kk = 0; kk < 16; kk++) {
            float a[8];
            *(float4*)&a[0] = *(const float4*)&As[kk][8 * ty];
            *(float4*)&a[4] = *(const float4*)&As[kk][8 * ty + 4];
            ulonglong2 bA = *(const ulonglong2*)&Ws[kk][8 * tx];
            ulonglong2 bB = *(const ulonglong2*)&Ws[kk][8 * tx + 4];
            #pragma unroll
            for (int i = 0; i < 8; i++) {
                unsigned long long ad = pk2(a[i], a[i]);
                fma2(acc2[i][0], ad, bA.x);
                fma2(acc2[i][1], ad, bA.y);
                fma2(acc2[i][2], ad, bB.x);
                fma2(acc2[i][3], ad, bB.y);
            }
        }
        __syncthreads();
    }
    float bv[8];
    #pragma unroll
    for (int j = 0; j < 8; j++) {
        int n = n0 + 8 * tx + j;
        bv[j] = b1[n] + b2[n];
    }
    #pragma unroll
    for (int i = 0; i < 8; i++) {
        size_t row = (size_t)(m0 + 8 * ty + i) * 1024 + n0 + 8 * tx;
        float2 p0 = upk(acc2[i][0]), p1 = upk(acc2[i][1]);
        float2 p2 = upk(acc2[i][2]), p3 = upk(acc2[i][3]);
        float4 o0 = make_float4(p0.x + bv[0], p0.y + bv[1], p1.x + bv[2], p1.y + bv[3]);
        float4 o1 = make_float4(p2.x + bv[4], p2.y + bv[5], p3.x + bv[6], p3.y + bv[7]);
        *(float4*)&g_xp[row]     = o0;
        *(float4*)&g_xp[row + 4] = o1;
    }
}

// ---------------- persistent LSTM layer (v6: f32x2 GEMM, k-major h tile) ----------------
#define HSK 36
#define PS2_OFF (256 * HSK)
#define CS_OFF2 (PS2_OFF + 8 * 16 * 64 * 2)
#define LSTM_SMEM ((256 * HSK + 8 * 16 * 64 * 2 + 512) * 4)

__device__ __forceinline__ float sigf(float x) {
    return __fdividef(1.f, 1.f + __expf(-x));
}
__device__ __forceinline__ float tanhfast(float x) {
    return 2.f * sigf(2.f * x) - 1.f;
}

__global__ __launch_bounds__(256) void lstm_persist_kernel(
    int layer, unsigned base, const float* __restrict__ Whh) {
    extern __shared__ float sm[];
    float* hs_s = sm;                 // [256][HSK] k-major h_prev tile
    float* ps2  = sm + PS2_OFF;       // [8][16][64][2] split-K partials
    float* c_s  = sm + CS_OFF2;       // [512] cell state

    int tid = threadIdx.x;
    int q = tid >> 5;
    int lane = tid & 31;
    int bt = blockIdx.x >> 4, ht = blockIdx.x & 15;
    int b0 = bt * 32, h0 = ht * 16;
    float* hs = layer ? g_y0 : g_hs0;

    // ---- Whh slice, duplicate-packed (once per launch) ----
    unsigned long long wd0[32], wd1[32];
    {
        int gc0 = 2 * lane, gc1 = 2 * lane + 1;
        const float* r0 = Whh + (size_t)((gc0 >> 4) * 256 + h0 + (gc0 & 15)) * 256 + q * 32;
        const float* r1 = Whh + (size_t)((gc1 >> 4) * 256 + h0 + (gc1 & 15)) * 256 + q * 32;
        #pragma unroll
        for (int k = 0; k < 32; k++) {
            float w0 = r0[k], w1 = r1[k];
            wd0[k] = pk2(w0, w0);
            wd1[k] = pk2(w1, w1);
        }
    }
    c_s[2 * tid] = 0.f;
    c_s[2 * tid + 1] = 0.f;
    unsigned* cnt = &g_cnt[bt];

    int sb = tid & 31;
    int skq = tid >> 5;
    int ub0 = (2 * tid) >> 4, uj0 = (2 * tid) & 15;
    int ub1 = (2 * tid + 1) >> 4, uj1 = (2 * tid + 1) & 15;

    for (int t = 0; t < 77; t++) {
        // ---- prefetch xp for this step (independent of the barrier) ----
        const float* xp_t = g_xp + (size_t)t * 262144;
        const float* xr0 = xp_t + (size_t)(b0 + ub0) * 1024 + h0 + uj0;
        const float* xr1 = xp_t + (size_t)(b0 + ub1) * 1024 + h0 + uj1;
        float xi0 = xr0[0], xf0 = xr0[256], xg0 = xr0[512], xo0 = xr0[768];
        float xi1 = xr1[0], xf1 = xr1[256], xg1 = xr1[512], xo1 = xr1[768];

        // ---- wait for h(t-1) ----
        if (t > 0) {
            if (tid == 0) {
                unsigned target = base + 16u * (unsigned)t;
                while (*(volatile unsigned*)cnt < target) { }
                __threadfence();
            }
            __syncthreads();
        }

        // ---- stage h_prev into k-major tile ----
        if (t == 0) {
            #pragma unroll
            for (int i = 0; i < 32; i++)
                hs_s[(skq * 32 + i) * HSK + sb] = 0.f;
        } else {
            const float* srcp = hs + (size_t)(t - 1) * 65536 + (size_t)(b0 + sb) * 256 + skq * 32;
            #pragma unroll
            for (int i = 0; i < 32; i += 4) {
                float4 v = *(const float4*)&srcp[i];
                hs_s[(skq * 32 + i + 0) * HSK + sb] = v.x;
                hs_s[(skq * 32 + i + 1) * HSK + sb] = v.y;
                hs_s[(skq * 32 + i + 2) * HSK + sb] = v.z;
                hs_s[(skq * 32 + i + 3) * HSK + sb] = v.w;
            }
        }
        __syncthreads();

        // ---- split-K GEMM (f32x2): 8 groups of 4 batches ----
        {
            const float* apb = hs_s + (q * 32) * HSK;
            float* myps = ps2 + q * 2048;           // [16][64][2]
            int gc0 = 2 * lane, gc1 = 2 * lane + 1;
            #pragma unroll
            for (int grp = 0; grp < 8; grp++) {
                unsigned long long aA0 = 0ull, aA1 = 0ull, aB0 = 0ull, aB1 = 0ull;
                const float* ap = apb + grp * 4;
                #pragma unroll
                for (int k = 0; k < 32; k++) {
                    ulonglong2 av = *(const ulonglong2*)(ap + k * HSK);
                    fma2(aA0, av.x, wd0[k]);
                    fma2(aA1, av.y, wd0[k]);
                    fma2(aB0, av.x, wd1[k]);
                    fma2(aB1, av.y, wd1[k]);
                }
                int p0i = grp * 2, p1i = grp * 2 + 1;
                *(unsigned long long*)&myps[(p0i * 64 + gc0) * 2] = aA0;
                *(unsigned long long*)&myps[(p1i * 64 + gc0) * 2] = aA1;
                *(unsigned long long*)&myps[(p0i * 64 + gc1) * 2] = aB0;
                *(unsigned long long*)&myps[(p1i * 64 + gc1) * 2] = aB1;
            }
        }
        __syncthreads();

        // ---- pointwise: reduce 8 partials + prefetched xp; update c, write h ----
        {
            float* h_out = hs + (size_t)t * 65536;
            {
                int b = ub0, j = uj0, u = 2 * tid;
                int bp = (b >> 1), sel = (b & 1);
                float gi = xi0, gf = xf0, gg = xg0, go = xo0;
                #pragma unroll
                for (int qq = 0; qq < 8; qq++) {
                    const float* p = ps2 + qq * 2048 + (bp * 64) * 2 + sel;
                    gi += p[(j) * 2];
                    gf += p[(16 + j) * 2];
                    gg += p[(32 + j) * 2];
                    go += p[(48 + j) * 2];
                }
                float c = sigf(gf) * c_s[u] + sigf(gi) * tanhfast(gg);
                c_s[u] = c;
                h_out[(size_t)(b0 + b) * 256 + h0 + j] = sigf(go) * tanhfast(c);
            }
            {
                int b = ub1, j = uj1, u = 2 * tid + 1;
                int bp = (b >> 1), sel = (b & 1);
                float gi = xi1, gf = xf1, gg = xg1, go = xo1;
                #pragma unroll
                for (int qq = 0; qq < 8; qq++) {
                    const float* p = ps2 + qq * 2048 + (bp * 64) * 2 + sel;
                    gi += p[(j) * 2];
                    gf += p[(16 + j) * 2];
                    gg += p[(32 + j) * 2];
                    go += p[(48 + j) * 2];
                }
                float c = sigf(gf) * c_s[u] + sigf(gi) * tanhfast(gg);
                c_s[u] = c;
                h_out[(size_t)(b0 + b) * 256 + h0 + j] = sigf(go) * tanhfast(c);
            }
        }

        // ---- arrive (all threads fence their h stores, then tid0 signals) ----
        if (t < 76) {
            __threadfence();
            __syncthreads();
            if (tid == 0) atomicAdd(cnt, 1u);
        }
    }
}

// ---------------- FC head ----------------
__global__ __launch_bounds__(256) void fc_kernel(
    int stage, const float* __restrict__ W, const float* __restrict__ bias,
    float* __restrict__ dout) {
    __shared__ float As[32][33];
    __shared__ float Ws[32][33];
    const float* A; float* out; int K, N; int relu;
    if (stage == 0) { A = g_y0 + (size_t)76 * 65536; out = g_f1; K = 256; N = 512; relu = 1; }
    else if (stage == 1) { A = g_f1; out = g_f2; K = 512; N = 512; relu = 1; }
    else { A = g_f2; out = dout; K = 512; N = 256; relu = 0; }
    int n0 = blockIdx.x * 32, m0 = blockIdx.y * 32;
    int tid = threadIdx.x;
    int lrow = tid >> 3, lkq = tid & 7;
    int ty = tid >> 4, tx = tid & 15;
    float acc[2][2] = {{0.f, 0.f}, {0.f, 0.f}};
    for (int k0 = 0; k0 < K; k0 += 32) {
        __syncthreads();
        {
            float4 va = *(const float4*)&A[(size_t)(m0 + lrow) * K + k0 + 4 * lkq];
            As[lrow][4*lkq+0] = va.x; As[lrow][4*lkq+1] = va.y;
            As[lrow][4*lkq+2] = va.z; As[lrow][4*lkq+3] = va.w;
            float4 vw = *(const float4*)&W[(size_t)(n0 + lrow) * K + k0 + 4 * lkq];
            Ws[lrow][4*lkq+0] = vw.x; Ws[lrow][4*lkq+1] = vw.y;
            Ws[lrow][4*lkq+2] = vw.z; Ws[lrow][4*lkq+3] = vw.w;
        }
        __syncthreads();
        #pragma unroll
        for (int kk = 0; kk < 32; kk++) {
            float a0 = As[2*ty][kk], a1 = As[2*ty+1][kk];
            float w0 = Ws[2*tx][kk], w1 = Ws[2*tx+1][kk];
            acc[0][0] = fmaf(a0, w0, acc[0][0]);
            acc[0][1] = fmaf(a0, w1, acc[0][1]);
            acc[1][0] = fmaf(a1, w0, acc[1][0]);
            acc[1][1] = fmaf(a1, w1, acc[1][1]);
        }
    }
    #pragma unroll
    for (int i = 0; i < 2; i++) {
        #pragma unroll
        for (int j = 0; j < 2; j++) {
            int m = m0 + 2 * ty + i, n = n0 + 2 * tx + j;
            float v = acc[i][j] + bias[n];
            if (relu) v = fmaxf(v, 0.f);
            out[(size_t)m * N + n] = v;
        }
    }
}

// ---------------- launch ----------------
extern "C" void kernel_launch(void* const* d_in, const int* in_sizes, int n_in,
                              void* d_out, int out_size) {
    const float* x       = (const float*)d_in[0];
    const float* conv_w0 = (const float*)d_in[1];
    const float* conv_b0 = (const float*)d_in[2];
    const float* bn_g0   = (const float*)d_in[3];
    const float* bn_b0   = (const float*)d_in[4];
    const float* bn_m0   = (const float*)d_in[5];
    const float* bn_v0   = (const float*)d_in[6];
    const float* conv_w1 = (const float*)d_in[7];
    const float* conv_b1 = (const float*)d_in[8];
    const float* bn_g1   = (const float*)d_in[9];
    const float* bn_b1   = (const float*)d_in[10];
    const float* bn_m1   = (const float*)d_in[11];
    const float* bn_v1   = (const float*)d_in[12];
    const float* Wih0    = (const float*)d_in[13];
    const float* Whh0    = (const float*)d_in[14];
    const float* bih0    = (const float*)d_in[15];
    const float* bhh0    = (const float*)d_in[16];
    const float* Wih1    = (const float*)d_in[17];
    const float* Whh1    = (const float*)d_in[18];
    const float* bih1    = (const float*)d_in[19];
    const float* bhh1    = (const float*)d_in[20];
    const float* fc0_w   = (const float*)d_in[21];
    const float* fc0_b   = (const float*)d_in[22];
    const float* fc1_w   = (const float*)d_in[23];
    const float* fc1_b   = (const float*)d_in[24];
    const float* out_w   = (const float*)d_in[25];
    const float* out_b   = (const float*)d_in[26];
    float* out = (float*)d_out;

    cudaFuncSetAttribute(lstm_persist_kernel,
                         cudaFuncAttributeMaxDynamicSharedMemorySize, LSTM_SMEM);
    cudaFuncSetAttribute(conv1_kernel,
                         cudaFuncAttributeMaxDynamicSharedMemorySize, C1_SMEM);

    reset_cnt_kernel<<<1, 32>>>();
    conv0_kernel<<<dim3(5, 256), 256>>>(x, conv_w0, conv_b0, bn_g0, bn_b0, bn_m0, bn_v0);
    conv1_kernel<<<dim3(5, 256), 256, C1_SMEM>>>(conv_w1, conv_b1, bn_g1, bn_b1, bn_m1, bn_v1);

    gemm_xproj_kernel<<<dim3(8, 154), 256>>>(0, Wih0, bih0, bhh0);
    lstm_persist_kernel<<<128, 256, LSTM_SMEM>>>(0, 0u, Whh0);

    gemm_xproj_kernel<<<dim3(8, 154), 256>>>(1, Wih1, bih1, bhh1);
    lstm_persist_kernel<<<128, 256, LSTM_SMEM>>>(1, 16u * 76u, Whh1);

    fc_kernel<<<dim3(16, 8), 256>>>(0, fc0_w, fc0_b, out);
    fc_kernel<<<dim3(16, 8), 256>>>(1, fc1_w, fc1_b, out);
    fc_kernel<<<dim3(8, 8), 256>>>(2, out_w, out_b, out);
}

// round 10
// speedup vs baseline: 1.3978x; 1.0105x over previous
#include <cuda_runtime.h>
#include <math.h>

// ---------------- scratch (static __device__, allocation-free) ----------------
__device__ float g_y0 [256 * 64 * 624];     // conv block 0 out (b,c,p); reused as layer1 hs
__device__ float g_seq[77 * 256 * 128];     // conv block 1 out, (t,b,c)
__device__ float g_xp [77 * 256 * 1024];    // lstm input projection (t,b,4H), reused per layer
__device__ float g_hs0[77 * 256 * 256];     // layer0 hidden sequence (t,b,H)
__device__ float g_f1 [256 * 512];
__device__ float g_f2 [256 * 512];
__device__ unsigned g_cnt[8];               // per-batch-tile arrival counters

// SG(11,3) interior smoothing taps (symmetric): [-36,9,44,69,84,89,84,69,44,9,-36]/429
__constant__ float c_sg[11] = {
    -36.f/429.f, 9.f/429.f, 44.f/429.f, 69.f/429.f, 84.f/429.f, 89.f/429.f,
    84.f/429.f, 69.f/429.f, 44.f/429.f, 9.f/429.f, -36.f/429.f };

// ---------------- f32x2 packed-math helpers ----------------
__device__ __forceinline__ unsigned long long pk2(float a, float b) {
    unsigned long long r;
    asm("mov.b64 %0, {%1, %2};" : "=l"(r) : "f"(a), "f"(b));
    return r;
}
__device__ __forceinline__ void fma2(unsigned long long& d,
                                     unsigned long long a, unsigned long long b) {
    asm("fma.rn.f32x2 %0, %1, %2, %0;" : "+l"(d) : "l"(a), "l"(b));
}
__device__ __forceinline__ float2 upk(unsigned long long v) {
    float2 r;
    asm("mov.b64 {%0, %1}, %2;" : "=f"(r.x), "=f"(r.y) : "l"(v));
    return r;
}

// ---------------- savgol edge fit (cols 0..4 only; high edge is never consumed) ----------------
__device__ __forceinline__ void sg_fit(const float* __restrict__ xw, double a[4]) {
    double m0 = 0, m1 = 0, m2 = 0, m3 = 0;
    #pragma unroll
    for (int w = 0; w < 11; w++) {
        double y = (double)xw[w]; double t = (double)w;
        m0 += y; m1 += y * t; m2 += y * t * t; m3 += y * t * t * t;
    }
    double M[4][5] = {
        {11.0,    55.0,     385.0,     3025.0,    m0},
        {55.0,    385.0,    3025.0,    25333.0,   m1},
        {385.0,   3025.0,   25333.0,   220825.0,  m2},
        {3025.0,  25333.0,  220825.0,  1978405.0, m3}};
    #pragma unroll
    for (int i = 0; i < 4; i++) {
        double p = M[i][i];
        #pragma unroll
        for (int j = i; j < 5; j++) M[i][j] /= p;
        #pragma unroll
        for (int r = 0; r < 4; r++) {
            if (r != i) {
                double f = M[r][i];
                #pragma unroll
                for (int j = i; j < 5; j++) M[r][j] -= f * M[i][j];
            }
        }
    }
    a[0] = M[0][4]; a[1] = M[1][4]; a[2] = M[2][4]; a[3] = M[3][4];
}

// ---------------- conv block 0 (savgol fused in; also resets lstm counters) ----------------
__global__ __launch_bounds__(256) void conv0_kernel(
    const float* __restrict__ x,
    const float* __restrict__ w, const float* __restrict__ bias,
    const float* __restrict__ bg, const float* __restrict__ bb,
    const float* __restrict__ bm, const float* __restrict__ bv) {
    __shared__ float xs[2080];
    __shared__ float in_s[2064];
    __shared__ float ws[64][17];
    __shared__ float scs[64], shs[64], bss[64];
    int b = blockIdx.y;
    int p0 = blockIdx.x * 128;
    int tid = threadIdx.x;
    if (blockIdx.x == 0 && blockIdx.y == 0 && tid < 8) g_cnt[tid] = 0;
    int base = 16 * p0;
    const float* xr = x + (size_t)b * 10000;
    for (int i = tid; i < 2074; i += 256) {
        int col = base - 5 + i;
        xs[i] = (col >= 0 && col < 10000) ? xr[col] : 0.f;
    }
    for (int i = tid; i < 1024; i += 256) ws[i >> 4][i & 15] = w[i];
    if (tid < 64) {
        float sc = bg[tid] * rsqrtf(bv[tid] + 1e-5f);
        scs[tid] = sc;
        shs[tid] = bb[tid] - bm[tid] * sc;
        bss[tid] = bias[tid];
    }
    __syncthreads();
    for (int i = tid; i < 2064; i += 256) {
        float acc = 0.f;
        #pragma unroll
        for (int j = 0; j < 11; j++) acc = fmaf(xs[i + j], c_sg[j], acc);
        in_s[i] = acc;
    }
    if (blockIdx.x == 0 && tid < 5) {
        double a[4]; sg_fit(xs + 5, a);
        double t = (double)tid;
        in_s[tid] = (float)(a[0] + t * (a[1] + t * (a[2] + t * a[3])));
    }
    __syncthreads();
    int p = p0 + (tid & 127);
    int cb = (tid >> 7) * 32;
    if (p >= 624) return;
    float xv[24];
    int lb = 16 * (tid & 127);
    #pragma unroll
    for (int k = 0; k < 24; k++) xv[k] = in_s[lb + k];
    #pragma unroll 4
    for (int c = cb; c < cb + 32; c++) {
        float s1 = 0.f, s2 = 0.f;
        #pragma unroll
        for (int k = 0; k < 16; k++) {
            float wv = ws[c][k];
            s1 = fmaf(wv, xv[k], s1);
            s2 = fmaf(wv, xv[k + 8], s2);
        }
        float m = fmaxf(fmaxf(s1, s2) + bss[c], 0.f);
        g_y0[((size_t)b * 64 + c) * 624 + p] = scs[c] * m + shs[c];
    }
}

// ---------------- conv block 1 (16 pooled/CTA, 4oc x 4pos) ----------------
#define C1_IN   (64 * 132)
#define C1_WS   (4 * 8 * 128)
#define C1_SMEM ((C1_IN + C1_WS + 3 * 128) * 4)

__global__ __launch_bounds__(256) void conv1_kernel(
    const float* __restrict__ w, const float* __restrict__ bias,
    const float* __restrict__ bg, const float* __restrict__ bb,
    const float* __restrict__ bm, const float* __restrict__ bv) {
    extern __shared__ float c1s[];
    float* in_s = c1s;                       // [64][132]
    float* ws   = c1s + C1_IN;               // [4][8][128]
    float* scs  = ws + C1_WS;
    float* shs  = scs + 128;
    float* bss  = shs + 128;

    int b = blockIdx.y;
    int p0 = blockIdx.x * 16;
    int tid = threadIdx.x;
    int cg = tid & 31, pg = tid >> 5;

    for (int i = tid; i < C1_IN; i += 256) {
        int ic = i / 132, cc = i % 132;
        int col = 8 * p0 + cc;
        in_s[i] = (col < 624) ? g_y0[((size_t)b * 64 + ic) * 624 + col] : 0.f;
    }
    if (tid < 128) {
        float sc = bg[tid] * rsqrtf(bv[tid] + 1e-5f);
        scs[tid] = sc;
        shs[tid] = bb[tid] - bm[tid] * sc;
        bss[tid] = bias[tid];
    }
    float acc[4][4];
    #pragma unroll
    for (int i = 0; i < 4; i++)
        #pragma unroll
        for (int j = 0; j < 4; j++) acc[i][j] = 0.f;

    int ocl = tid & 127, half = tid >> 7;
    for (int ic0 = 0; ic0 < 64; ic0 += 4) {
        __syncthreads();
        #pragma unroll
        for (int il = 0; il < 2; il++) {
            int icl = half * 2 + il;
            const float4* src = (const float4*)(w + ((size_t)ocl * 64 + ic0 + icl) * 8);
            float4 v0 = src[0], v1 = src[1];
            float* wd = ws + icl * 1024 + ocl;
            wd[0 * 128] = v0.x; wd[1 * 128] = v0.y; wd[2 * 128] = v0.z; wd[3 * 128] = v0.w;
            wd[4 * 128] = v1.x; wd[5 * 128] = v1.y; wd[6 * 128] = v1.z; wd[7 * 128] = v1.w;
        }
        __syncthreads();
        #pragma unroll
        for (int icl = 0; icl < 4; icl++) {
            #pragma unroll
            for (int t = 0; t < 8; t++) {
                float4 w4 = *(const float4*)&ws[icl * 1024 + t * 128 + cg * 4];
                const float* ir = in_s + (ic0 + icl) * 132 + 16 * pg + t;
                #pragma unroll
                for (int qc = 0; qc < 4; qc++) {
                    float iv = ir[4 * qc];
                    acc[0][qc] = fmaf(w4.x, iv, acc[0][qc]);
                    acc[1][qc] = fmaf(w4.y, iv, acc[1][qc]);
                    acc[2][qc] = fmaf(w4.z, iv, acc[2][qc]);
                    acc[3][qc] = fmaf(w4.w, iv, acc[3][qc]);
                }
            }
        }
    }
    #pragma unroll
    for (int pp = 0; pp < 2; pp++) {
        int p = p0 + 2 * pg + pp;
        if (p >= 77) continue;
        float ov[4];
        #pragma unroll
        for (int i = 0; i < 4; i++) {
            int oc = 4 * cg + i;
            float m = fmaxf(acc[i][2 * pp], acc[i][2 * pp + 1]);
            float v = fmaxf(m + bss[oc], 0.f);
            ov[i] = scs[oc] * v + shs[oc];
        }
        *(float4*)&g_seq[((size_t)p * 256 + b) * 128 + 4 * cg] =
            make_float4(ov[0], ov[1], ov[2], ov[3]);
    }
}

// ---------------- input-projection GEMM (f32x2, double-buffered smem) ----------------
#define XP_BUF (16 * 132)
#define XP_SMEM (4 * XP_BUF * 4)   // 2 buffers x (As+Ws) x 16x132 floats

__global__ __launch_bounds__(256) void gemm_xproj_kernel(
    int src, const float* __restrict__ Wih,
    const float* __restrict__ b1, const float* __restrict__ b2) {
    extern __shared__ float xsm[];
    float* AsB = xsm;                 // [2][16][132]
    float* WsB = xsm + 2 * XP_BUF;    // [2][16][132]
    const int K = src ? 256 : 128;
    const float* A = src ? g_hs0 : g_seq;
    int n0 = blockIdx.x * 128, m0 = blockIdx.y * 128;
    int tid = threadIdx.x;
    int lr = tid >> 2, lq = tid & 3;
    int tx = tid & 15, ty = tid >> 4;
    unsigned long long acc2[8][4];
    #pragma unroll
    for (int i = 0; i < 8; i++)
        #pragma unroll
        for (int j = 0; j < 4; j++) acc2[i][j] = 0ull;

    const float* a0p = A + (size_t)(m0 + lr) * K + 4 * lq;
    const float* a1p = A + (size_t)(m0 + lr + 64) * K + 4 * lq;
    const float* w0p = Wih + (size_t)(n0 + lr) * K + 4 * lq;
    const float* w1p = Wih + (size_t)(n0 + lr + 64) * K + 4 * lq;

    float4 pa0 = *(const float4*)a0p;
    float4 pa1 = *(const float4*)a1p;
    float4 pw0 = *(const float4*)w0p;
    float4 pw1 = *(const float4*)w1p;

    int nch = K >> 4;
    for (int c = 0; c < nch; c++) {
        float* As = AsB + (c & 1) * XP_BUF;
        float* Ws = WsB + (c & 1) * XP_BUF;
        As[(4*lq+0)*132 + lr] = pa0.x; As[(4*lq+1)*132 + lr] = pa0.y;
        As[(4*lq+2)*132 + lr] = pa0.z; As[(4*lq+3)*132 + lr] = pa0.w;
        As[(4*lq+0)*132 + lr+64] = pa1.x; As[(4*lq+1)*132 + lr+64] = pa1.y;
        As[(4*lq+2)*132 + lr+64] = pa1.z; As[(4*lq+3)*132 + lr+64] = pa1.w;
        Ws[(4*lq+0)*132 + lr] = pw0.x; Ws[(4*lq+1)*132 + lr] = pw0.y;
        Ws[(4*lq+2)*132 + lr] = pw0.z; Ws[(4*lq+3)*132 + lr] = pw0.w;
        Ws[(4*lq+0)*132 + lr+64] = pw1.x; Ws[(4*lq+1)*132 + lr+64] = pw1.y;
        Ws[(4*lq+2)*132 + lr+64] = pw1.z; Ws[(4*lq+3)*132 + lr+64] = pw1.w;
        __syncthreads();
        if (c + 1 < nch) {
            int k0 = (c + 1) * 16;
            pa0 = *(const float4*)(a0p + k0);
            pa1 = *(const float4*)(a1p + k0);
            pw0 = *(const float4*)(w0p + k0);
            pw1 = *(const float4*)(w1p + k0);
        }
        #pragma unroll
        for (int kk = 0; kk < 16; kk++) {
            float a[8];
            *(float4*)&a[0] = *(const float4*)&As[kk*132 + 8 * ty];
            *(float4*)&a[4] = *(const float4*)&As[kk*132 + 8 * ty + 4];
            ulonglong2 bA = *(const ulonglong2*)&Ws[kk*132 + 8 * tx];
            ulonglong2 bB = *(const ulonglong2*)&Ws[kk*132 + 8 * tx + 4];
            #pragma unroll
            for (int i = 0; i < 8; i++) {
                unsigned long long ad = pk2(a[i], a[i]);
                fma2(acc2[i][0], ad, bA.x);
                fma2(acc2[i][1], ad, bA.y);
                fma2(acc2[i][2], ad, bB.x);
                fma2(acc2[i][3], ad, bB.y);
            }
        }
    }
    float bv[8];
    #pragma unroll
    for (int j = 0; j < 8; j++) {
        int n = n0 + 8 * tx + j;
        bv[j] = b1[n] + b2[n];
    }
    #pragma unroll
    for (int i = 0; i < 8; i++) {
        size_t row = (size_t)(m0 + 8 * ty + i) * 1024 + n0 + 8 * tx;
        float2 p0 = upk(acc2[i][0]), p1 = upk(acc2[i][1]);
        float2 p2 = upk(acc2[i][2]), p3 = upk(acc2[i][3]);
        float4 o0 = make_float4(p0.x + bv[0], p0.y + bv[1], p1.x + bv[2], p1.y + bv[3]);
        float4 o1 = make_float4(p2.x + bv[4], p2.y + bv[5], p3.x + bv[6], p3.y + bv[7]);
        *(float4*)&g_xp[row]     = o0;
        *(float4*)&g_xp[row + 4] = o1;
    }
}

// ---------------- persistent LSTM layer (v6: f32x2 GEMM, k-major h tile) ----------------
#define HSK 36
#define PS2_OFF (256 * HSK)
#define CS_OFF2 (PS2_OFF + 8 * 16 * 64 * 2)
#define LSTM_SMEM ((256 * HSK + 8 * 16 * 64 * 2 + 512) * 4)

__device__ __forceinline__ float sigf(float x) {
    return __fdividef(1.f, 1.f + __expf(-x));
}
__device__ __forceinline__ float tanhfast(float x) {
    return 2.f * sigf(2.f * x) - 1.f;
}

__global__ __launch_bounds__(256) void lstm_persist_kernel(
    int layer, unsigned base, const float* __restrict__ Whh) {
    extern __shared__ float sm[];
    float* hs_s = sm;                 // [256][HSK] k-major h_prev tile
    float* ps2  = sm + PS2_OFF;       // [8][16][64][2] split-K partials
    float* c_s  = sm + CS_OFF2;       // [512] cell state

    int tid = threadIdx.x;
    int q = tid >> 5;
    int lane = tid & 31;
    int bt = blockIdx.x >> 4, ht = blockIdx.x & 15;
    int b0 = bt * 32, h0 = ht * 16;
    float* hs = layer ? g_y0 : g_hs0;

    // ---- Whh slice, duplicate-packed (once per launch) ----
    unsigned long long wd0[32], wd1[32];
    {
        int gc0 = 2 * lane, gc1 = 2 * lane + 1;
        const float* r0 = Whh + (size_t)((gc0 >> 4) * 256 + h0 + (gc0 & 15)) * 256 + q * 32;
        const float* r1 = Whh + (size_t)((gc1 >> 4) * 256 + h0 + (gc1 & 15)) * 256 + q * 32;
        #pragma unroll
        for (int k = 0; k < 32; k++) {
            float w0 = r0[k], w1 = r1[k];
            wd0[k] = pk2(w0, w0);
            wd1[k] = pk2(w1, w1);
        }
    }
    c_s[2 * tid] = 0.f;
    c_s[2 * tid + 1] = 0.f;
    unsigned* cnt = &g_cnt[bt];

    int sb = tid & 31;
    int skq = tid >> 5;
    int ub0 = (2 * tid) >> 4, uj0 = (2 * tid) & 15;
    int ub1 = (2 * tid + 1) >> 4, uj1 = (2 * tid + 1) & 15;

    for (int t = 0; t < 77; t++) {
        // ---- prefetch xp for this step (independent of the barrier) ----
        const float* xp_t = g_xp + (size_t)t * 262144;
        const float* xr0 = xp_t + (size_t)(b0 + ub0) * 1024 + h0 + uj0;
        const float* xr1 = xp_t + (size_t)(b0 + ub1) * 1024 + h0 + uj1;
        float xi0 = xr0[0], xf0 = xr0[256], xg0 = xr0[512], xo0 = xr0[768];
        float xi1 = xr1[0], xf1 = xr1[256], xg1 = xr1[512], xo1 = xr1[768];

        // ---- wait for h(t-1) ----
        if (t > 0) {
            if (tid == 0) {
                unsigned target = base + 16u * (unsigned)t;
                while (*(volatile unsigned*)cnt < target) { }
                __threadfence();
            }
            __syncthreads();
        }

        // ---- stage h_prev into k-major tile ----
        if (t == 0) {
            #pragma unroll
            for (int i = 0; i < 32; i++)
                hs_s[(skq * 32 + i) * HSK + sb] = 0.f;
        } else {
            const float* srcp = hs + (size_t)(t - 1) * 65536 + (size_t)(b0 + sb) * 256 + skq * 32;
            #pragma unroll
            for (int i = 0; i < 32; i += 4) {
                float4 v = *(const float4*)&srcp[i];
                hs_s[(skq * 32 + i + 0) * HSK + sb] = v.x;
                hs_s[(skq * 32 + i + 1) * HSK + sb] = v.y;
                hs_s[(skq * 32 + i + 2) * HSK + sb] = v.z;
                hs_s[(skq * 32 + i + 3) * HSK + sb] = v.w;
            }
        }
        __syncthreads();

        // ---- split-K GEMM (f32x2): 8 groups of 4 batches ----
        {
            const float* apb = hs_s + (q * 32) * HSK;
            float* myps = ps2 + q * 2048;           // [16][64][2]
            int gc0 = 2 * lane, gc1 = 2 * lane + 1;
            #pragma unroll
            for (int grp = 0; grp < 8; grp++) {
                unsigned long long aA0 = 0ull, aA1 = 0ull, aB0 = 0ull, aB1 = 0ull;
                const float* ap = apb + grp * 4;
                #pragma unroll
                for (int k = 0; k < 32; k++) {
                    ulonglong2 av = *(const ulonglong2*)(ap + k * HSK);
                    fma2(aA0, av.x, wd0[k]);
                    fma2(aA1, av.y, wd0[k]);
                    fma2(aB0, av.x, wd1[k]);
                    fma2(aB1, av.y, wd1[k]);
                }
                int p0i = grp * 2, p1i = grp * 2 + 1;
                *(unsigned long long*)&myps[(p0i * 64 + gc0) * 2] = aA0;
                *(unsigned long long*)&myps[(p1i * 64 + gc0) * 2] = aA1;
                *(unsigned long long*)&myps[(p0i * 64 + gc1) * 2] = aB0;
                *(unsigned long long*)&myps[(p1i * 64 + gc1) * 2] = aB1;
            }
        }
        __syncthreads();

        // ---- pointwise: reduce 8 partials + prefetched xp; update c, write h ----
        {
            float* h_out = hs + (size_t)t * 65536;
            {
                int b = ub0, j = uj0, u = 2 * tid;
                int bp = (b >> 1), sel = (b & 1);
                float gi = xi0, gf = xf0, gg = xg0, go = xo0;
                #pragma unroll
                for (int qq = 0; qq < 8; qq++) {
                    const float* p = ps2 + qq * 2048 + (bp * 64) * 2 + sel;
                    gi += p[(j) * 2];
                    gf += p[(16 + j) * 2];
                    gg += p[(32 + j) * 2];
                    go += p[(48 + j) * 2];
                }
                float c = sigf(gf) * c_s[u] + sigf(gi) * tanhfast(gg);
                c_s[u] = c;
                h_out[(size_t)(b0 + b) * 256 + h0 + j] = sigf(go) * tanhfast(c);
            }
            {
                int b = ub1, j = uj1, u = 2 * tid + 1;
                int bp = (b >> 1), sel = (b & 1);
                float gi = xi1, gf = xf1, gg = xg1, go = xo1;
                #pragma unroll
                for (int qq = 0; qq < 8; qq++) {
                    const float* p = ps2 + qq * 2048 + (bp * 64) * 2 + sel;
                    gi += p[(j) * 2];
                    gf += p[(16 + j) * 2];
                    gg += p[(32 + j) * 2];
                    go += p[(48 + j) * 2];
                }
                float c = sigf(gf) * c_s[u] + sigf(gi) * tanhfast(gg);
                c_s[u] = c;
                h_out[(size_t)(b0 + b) * 256 + h0 + j] = sigf(go) * tanhfast(c);
            }
        }

        // ---- arrive (syncthreads orders block stores; tid0 fence publishes) ----
        if (t < 76) {
            __syncthreads();
            if (tid == 0) {
                __threadfence();
                atomicAdd(cnt, 1u);
            }
        }
    }
}

// ---------------- FC head ----------------
__global__ __launch_bounds__(256) void fc_kernel(
    int stage, const float* __restrict__ W, const float* __restrict__ bias,
    float* __restrict__ dout) {
    __shared__ float As[32][33];
    __shared__ float Ws[32][33];
    const float* A; float* out; int K, N; int relu;
    if (stage == 0) { A = g_y0 + (size_t)76 * 65536; out = g_f1; K = 256; N = 512; relu = 1; }
    else if (stage == 1) { A = g_f1; out = g_f2; K = 512; N = 512; relu = 1; }
    else { A = g_f2; out = dout; K = 512; N = 256; relu = 0; }
    int n0 = blockIdx.x * 32, m0 = blockIdx.y * 32;
    int tid = threadIdx.x;
    int lrow = tid >> 3, lkq = tid & 7;
    int ty = tid >> 4, tx = tid & 15;
    float acc[2][2] = {{0.f, 0.f}, {0.f, 0.f}};
    for (int k0 = 0; k0 < K; k0 += 32) {
        __syncthreads();
        {
            float4 va = *(const float4*)&A[(size_t)(m0 + lrow) * K + k0 + 4 * lkq];
            As[lrow][4*lkq+0] = va.x; As[lrow][4*lkq+1] = va.y;
            As[lrow][4*lkq+2] = va.z; As[lrow][4*lkq+3] = va.w;
            float4 vw = *(const float4*)&W[(size_t)(n0 + lrow) * K + k0 + 4 * lkq];
            Ws[lrow][4*lkq+0] = vw.x; Ws[lrow][4*lkq+1] = vw.y;
            Ws[lrow][4*lkq+2] = vw.z; Ws[lrow][4*lkq+3] = vw.w;
        }
        __syncthreads();
        #pragma unroll
        for (int kk = 0; kk < 32; kk++) {
            float a0 = As[2*ty][kk], a1 = As[2*ty+1][kk];
            float w0 = Ws[2*tx][kk], w1 = Ws[2*tx+1][kk];
            acc[0][0] = fmaf(a0, w0, acc[0][0]);
            acc[0][1] = fmaf(a0, w1, acc[0][1]);
            acc[1][0] = fmaf(a1, w0, acc[1][0]);
            acc[1][1] = fmaf(a1, w1, acc[1][1]);
        }
    }
    #pragma unroll
    for (int i = 0; i < 2; i++) {
        #pragma unroll
        for (int j = 0; j < 2; j++) {
            int m = m0 + 2 * ty + i, n = n0 + 2 * tx + j;
            float v = acc[i][j] + bias[n];
            if (relu) v = fmaxf(v, 0.f);
            out[(size_t)m * N + n] = v;
        }
    }
}

// ---------------- launch ----------------
extern "C" void kernel_launch(void* const* d_in, const int* in_sizes, int n_in,
                              void* d_out, int out_size) {
    const float* x       = (const float*)d_in[0];
    const float* conv_w0 = (const float*)d_in[1];
    const float* conv_b0 = (const float*)d_in[2];
    const float* bn_g0   = (const float*)d_in[3];
    const float* bn_b0   = (const float*)d_in[4];
    const float* bn_m0   = (const float*)d_in[5];
    const float* bn_v0   = (const float*)d_in[6];
    const float* conv_w1 = (const float*)d_in[7];
    const float* conv_b1 = (const float*)d_in[8];
    const float* bn_g1   = (const float*)d_in[9];
    const float* bn_b1   = (const float*)d_in[10];
    const float* bn_m1   = (const float*)d_in[11];
    const float* bn_v1   = (const float*)d_in[12];
    const float* Wih0    = (const float*)d_in[13];
    const float* Whh0    = (const float*)d_in[14];
    const float* bih0    = (const float*)d_in[15];
    const float* bhh0    = (const float*)d_in[16];
    const float* Wih1    = (const float*)d_in[17];
    const float* Whh1    = (const float*)d_in[18];
    const float* bih1    = (const float*)d_in[19];
    const float* bhh1    = (const float*)d_in[20];
    const float* fc0_w   = (const float*)d_in[21];
    const float* fc0_b   = (const float*)d_in[22];
    const float* fc1_w   = (const float*)d_in[23];
    const float* fc1_b   = (const float*)d_in[24];
    const float* out_w   = (const float*)d_in[25];
    const float* out_b   = (const float*)d_in[26];
    float* out = (float*)d_out;

    cudaFuncSetAttribute(lstm_persist_kernel,
                         cudaFuncAttributeMaxDynamicSharedMemorySize, LSTM_SMEM);
    cudaFuncSetAttribute(conv1_kernel,
                         cudaFuncAttributeMaxDynamicSharedMemorySize, C1_SMEM);
    cudaFuncSetAttribute(gemm_xproj_kernel,
                         cudaFuncAttributeMaxDynamicSharedMemorySize, XP_SMEM);

    conv0_kernel<<<dim3(5, 256), 256>>>(x, conv_w0, conv_b0, bn_g0, bn_b0, bn_m0, bn_v0);
    conv1_kernel<<<dim3(5, 256), 256, C1_SMEM>>>(conv_w1, conv_b1, bn_g1, bn_b1, bn_m1, bn_v1);

    gemm_xproj_kernel<<<dim3(8, 154), 256, XP_SMEM>>>(0, Wih0, bih0, bhh0);
    lstm_persist_kernel<<<128, 256, LSTM_SMEM>>>(0, 0u, Whh0);

    gemm_xproj_kernel<<<dim3(8, 154), 256, XP_SMEM>>>(1, Wih1, bih1, bhh1);
    lstm_persist_kernel<<<128, 256, LSTM_SMEM>>>(1, 16u * 76u, Whh1);

    fc_kernel<<<dim3(16, 8), 256>>>(0, fc0_w, fc0_b, out);
    fc_kernel<<<dim3(16, 8), 256>>>(1, fc1_w, fc1_b, out);
    fc_kernel<<<dim3(8, 8), 256>>>(2, out_w, out_b, out);
}